// round 3
// baseline (speedup 1.0000x reference)
#include <cuda_runtime.h>
#include <cstdint>

#define BATCHN 4
#define SEQL   2048
#define EMB    1024
#define NHEAD  16
#define DKH    64
#define MROWS  (BATCHN*SEQL)   /* 8192 */

// ---------------- scratch (static device globals; no runtime allocation) ----
__device__ float g_q[(size_t)BATCHN*NHEAD*SEQL*DKH];     // [b,h,s,d]
__device__ float g_k[(size_t)BATCHN*NHEAD*SEQL*DKH];
__device__ float g_v[(size_t)BATCHN*NHEAD*SEQL*DKH];
__device__ float g_attn[(size_t)MROWS*EMB];              // [b,s,h*d]

// ---------------- helpers ---------------------------------------------------
__device__ __forceinline__ unsigned f2tf(float x) {
    unsigned r;
    asm("cvt.rna.tf32.f32 %0, %1;" : "=r"(r) : "f"(x));
    return r;
}
__device__ __forceinline__ void split_tf32(float x, unsigned &hi, unsigned &lo) {
    hi = f2tf(x);
    lo = f2tf(x - __uint_as_float(hi));
}
__device__ __forceinline__ void mma8(float c[4], const unsigned a[4], const unsigned b[2]) {
    asm volatile(
        "mma.sync.aligned.m16n8k8.row.col.f32.tf32.tf32.f32 "
        "{%0,%1,%2,%3},{%4,%5,%6,%7},{%8,%9},{%0,%1,%2,%3};\n"
        : "+f"(c[0]), "+f"(c[1]), "+f"(c[2]), "+f"(c[3])
        : "r"(a[0]), "r"(a[1]), "r"(a[2]), "r"(a[3]), "r"(b[0]), "r"(b[1]));
}
// permuted index for interleaved hi/lo pair layout (pair = k, k+4 adjacent)
__device__ __forceinline__ int qperm(int k) {   // returns even offset; +0 hi, +1 lo
    return (k >> 3) * 16 + (k & 3) * 4 + ((k >> 2) & 1) * 2;
}

// ---------------- GEMM (TF32 split), vectorized permuted SMEM ---------------
// MODE 0: per-head projections. sel = blockIdx.z + selbase -> q/k/v.
// MODE 1: output projection. A = g_attn, B = w_o, C = Cext.
#define LDA 80
#define LDB 80
#define GSM_FLOATS (128*LDA + 64*LDB)
#define GSM_BYTES  (GSM_FLOATS*4)

template<int MODE, int PASSES>
__global__ void __launch_bounds__(256) gemm_x3_kernel(
    const float* __restrict__ A0, const float* __restrict__ A1, const float* __restrict__ A2,
    const float* __restrict__ B0, const float* __restrict__ B1, const float* __restrict__ B2,
    float* __restrict__ Cext, int selbase)
{
    extern __shared__ float sm[];
    float* As = sm;              // [128][LDA] interleaved hi/lo, k-permuted
    float* Bs = sm + 128 * LDA;  // [64 cols][LDB]

    const int tid  = threadIdx.x;
    const int lane = tid & 31;
    const int warp = tid >> 5;
    const int wm = warp >> 1, wn = warp & 1;
    const int r8 = lane >> 2, lq = lane & 3;
    const int row0 = blockIdx.x * 128;

    const float* A;
    const float* Bt;
    int ldb, n0;
    float* Cq;
    if (MODE == 0) {
        int sel = blockIdx.z + selbase;
        A = sel == 0 ? A0 : (sel == 1 ? A1 : A2);
        const float* W = sel == 0 ? B0 : (sel == 1 ? B1 : B2);
        Bt = W + (size_t)blockIdx.y * EMB * 64; ldb = 64; n0 = 0;
        Cq = sel == 0 ? g_q : (sel == 1 ? g_k : g_v);
    } else {
        A = g_attn; Bt = B0; ldb = EMB; n0 = blockIdx.y * 64; Cq = Cext;
    }

    float acc[2][4][4];
#pragma unroll
    for (int i = 0; i < 2; i++)
#pragma unroll
        for (int j = 0; j < 4; j++)
#pragma unroll
            for (int r = 0; r < 4; r++) acc[i][j][r] = 0.f;

    float4 ra[4], rb[2];
    // prologue load (k0 = 0)
#pragma unroll
    for (int ii = 0; ii < 4; ii++) {
        int i = tid + ii * 256; int r = i >> 3, c4 = (i & 7) << 2;
        ra[ii] = *reinterpret_cast<const float4*>(A + (size_t)(row0 + r) * EMB + c4);
    }
#pragma unroll
    for (int ii = 0; ii < 2; ii++) {
        int i = tid + ii * 256; int r = i >> 4, c4 = (i & 15) << 2;
        rb[ii] = *reinterpret_cast<const float4*>(Bt + (size_t)r * ldb + n0 + c4);
    }

    for (int k0 = 0; k0 < EMB; k0 += 32) {
        // ---- split + store current tile (interleaved, permuted) ----
#pragma unroll
        for (int ii = 0; ii < 4; ii++) {
            int i = tid + ii * 256; int r = i >> 3, c4 = (i & 7) << 2;
            float v[4] = { ra[ii].x, ra[ii].y, ra[ii].z, ra[ii].w };
            int base = r * LDA + (c4 >> 3) * 16 + ((c4 >> 2) & 1) * 2;
#pragma unroll
            for (int j = 0; j < 4; j++) {
                unsigned h, l; split_tf32(v[j], h, l);
                *reinterpret_cast<float2*>(As + base + j * 4) =
                    make_float2(__uint_as_float(h), __uint_as_float(l));
            }
        }
#pragma unroll
        for (int ii = 0; ii < 2; ii++) {
            int i = tid + ii * 256; int r = i >> 4, c4 = (i & 15) << 2;
            float v[4] = { rb[ii].x, rb[ii].y, rb[ii].z, rb[ii].w };
            int q = qperm(r);
#pragma unroll
            for (int j = 0; j < 4; j++) {
                unsigned h, l; split_tf32(v[j], h, l);
                *reinterpret_cast<float2*>(Bs + (c4 + j) * LDB + q) =
                    make_float2(__uint_as_float(h), __uint_as_float(l));
            }
        }
        __syncthreads();

        // ---- prefetch next tile into regs ----
        if (k0 + 32 < EMB) {
#pragma unroll
            for (int ii = 0; ii < 4; ii++) {
                int i = tid + ii * 256; int r = i >> 3, c4 = (i & 7) << 2;
                ra[ii] = *reinterpret_cast<const float4*>(A + (size_t)(row0 + r) * EMB + k0 + 32 + c4);
            }
#pragma unroll
            for (int ii = 0; ii < 2; ii++) {
                int i = tid + ii * 256; int r = i >> 4, c4 = (i & 15) << 2;
                rb[ii] = *reinterpret_cast<const float4*>(Bt + (size_t)(k0 + 32 + r) * ldb + n0 + c4);
            }
        }

        // ---- compute ----
#pragma unroll
        for (int ks = 0; ks < 4; ks++) {
            const int fofs = ks * 16 + lq * 4;
            unsigned ah[2][4], al[2][4];
#pragma unroll
            for (int mt = 0; mt < 2; mt++) {
                int rbse = wm * 32 + mt * 16 + r8;
                float4 f0 = *reinterpret_cast<const float4*>(As + rbse * LDA + fofs);
                float4 f1 = *reinterpret_cast<const float4*>(As + (rbse + 8) * LDA + fofs);
                ah[mt][0] = __float_as_uint(f0.x); ah[mt][1] = __float_as_uint(f1.x);
                ah[mt][2] = __float_as_uint(f0.z); ah[mt][3] = __float_as_uint(f1.z);
                al[mt][0] = __float_as_uint(f0.y); al[mt][1] = __float_as_uint(f1.y);
                al[mt][2] = __float_as_uint(f0.w); al[mt][3] = __float_as_uint(f1.w);
            }
            unsigned bh[4][2], bl[4][2];
#pragma unroll
            for (int nt = 0; nt < 4; nt++) {
                int nb = wn * 32 + nt * 8 + r8;
                float4 f = *reinterpret_cast<const float4*>(Bs + nb * LDB + fofs);
                bh[nt][0] = __float_as_uint(f.x); bh[nt][1] = __float_as_uint(f.z);
                bl[nt][0] = __float_as_uint(f.y); bl[nt][1] = __float_as_uint(f.w);
            }
#pragma unroll
            for (int mt = 0; mt < 2; mt++)
#pragma unroll
                for (int nt = 0; nt < 4; nt++) {
                    mma8(acc[mt][nt], ah[mt], bh[nt]);
                    if (PASSES >= 2) mma8(acc[mt][nt], al[mt], bh[nt]);
                    if (PASSES >= 3) mma8(acc[mt][nt], ah[mt], bl[nt]);
                }
        }
        __syncthreads();
    }

    // ---- epilogue ----
#pragma unroll
    for (int mt = 0; mt < 2; mt++) {
        int r = row0 + wm * 32 + mt * 16 + r8;
#pragma unroll
        for (int nt = 0; nt < 4; nt++) {
            int c = wn * 32 + nt * 8 + lq * 2;
            if (MODE == 0) {
                int b = r >> 11, s = r & 2047;
                size_t base  = (((size_t)b * NHEAD + blockIdx.y) * SEQL + s) * DKH;
                size_t base2 = base + (size_t)8 * DKH;
                Cq[base + c]      = acc[mt][nt][0];
                Cq[base + c + 1]  = acc[mt][nt][1];
                Cq[base2 + c]     = acc[mt][nt][2];
                Cq[base2 + c + 1] = acc[mt][nt][3];
            } else {
                size_t base = (size_t)r * EMB + blockIdx.y * 64 + c;
                Cq[base]               = acc[mt][nt][0];
                Cq[base + 1]           = acc[mt][nt][1];
                Cq[base + 8 * EMB]     = acc[mt][nt][2];
                Cq[base + 8 * EMB + 1] = acc[mt][nt][3];
            }
        }
    }
}

// ---------------- flash attention (causal), vectorized permuted SMEM --------
// grid: (SEQL/64, BATCHN*NHEAD); block 128 (4 warps, 16 q-rows each)
#define LDK 144
#define LDV 144
#define LDP 72
#define F_K 0
#define F_V (64*LDK)
#define F_P (64*LDK + 64*LDV)
#define FSM_FLOATS (64*LDK + 64*LDV + 64*LDP)
#define FSM_BYTES  (FSM_FLOATS*4)
#define LOG2E 1.4426950408889634f

__global__ void __launch_bounds__(128) flash_kernel(const int* __restrict__ maskp)
{
    extern __shared__ float sm[];
    float* Ks = sm + F_K;   // [kv 0..63][qperm(d) 0..127]  hi/lo interleaved
    float* Vt = sm + F_V;   // [d 0..63][qperm(kv) 0..127]  hi/lo interleaved (transposed)
    float* Ps = sm + F_P;   // [row 0..63][p2(kv) 0..63]    single tf32 (also Q staging)

    const int tid  = threadIdx.x;
    const int lane = tid & 31;
    const int warp = tid >> 5;
    const int r8 = lane >> 2, lq = lane & 3;
    const int qt = blockIdx.x;
    const int bh = blockIdx.y;
    const int b = bh >> 4, h = bh & 15;
    const int q0 = qt * 64;

    const float* Q = g_q + (size_t)bh * SEQL * DKH;
    const float* K = g_k + (size_t)bh * SEQL * DKH;
    const float* V = g_v + (size_t)bh * SEQL * DKH;

    // ---- stage Q tile scaled by 8*log2(e), plain row-major in Ps ----
    const float qscale = 8.f * LOG2E;
#pragma unroll
    for (int ii = 0; ii < 8; ii++) {
        int i = tid + ii * 128;
        int r = i >> 4, c4 = (i & 15) << 2;
        float4 v4 = *reinterpret_cast<const float4*>(Q + (size_t)(q0 + r) * DKH + c4);
        float* d = Ps + r * LDP + c4;
        d[0] = v4.x * qscale; d[1] = v4.y * qscale; d[2] = v4.z * qscale; d[3] = v4.w * qscale;
    }
    __syncthreads();

    const int rl = warp * 16 + r8;
    unsigned qhi[8][4], qlo[8][4];
#pragma unroll
    for (int ks = 0; ks < 8; ks++) {
        split_tf32(Ps[rl * LDP + ks * 8 + lq],           qhi[ks][0], qlo[ks][0]);
        split_tf32(Ps[(rl + 8) * LDP + ks * 8 + lq],     qhi[ks][1], qlo[ks][1]);
        split_tf32(Ps[rl * LDP + ks * 8 + 4 + lq],       qhi[ks][2], qlo[ks][2]);
        split_tf32(Ps[(rl + 8) * LDP + ks * 8 + 4 + lq], qhi[ks][3], qlo[ks][3]);
    }

    float m[2] = { -1e30f, -1e30f };
    float l[2] = { 0.f, 0.f };
    float o[8][4];
#pragma unroll
    for (int i = 0; i < 8; i++)
#pragma unroll
        for (int j = 0; j < 4; j++) o[i][j] = 0.f;

    const int maskv = maskp[0];
    const int ntiles = maskv ? (qt + 1) : (SEQL / 64);

    for (int t = 0; t < ntiles; t++) {
        const int kv0 = t * 64;
        // ---- cooperative K / V load, split, permuted store ----
#pragma unroll
        for (int ii = 0; ii < 8; ii++) {
            int i = tid + ii * 128;
            int r = i >> 4, c4 = (i & 15) << 2;
            float4 k4 = *reinterpret_cast<const float4*>(K + (size_t)(kv0 + r) * DKH + c4);
            float kvl[4] = { k4.x, k4.y, k4.z, k4.w };
            int kbase = r * LDK + (c4 >> 3) * 16 + ((c4 >> 2) & 1) * 2;
#pragma unroll
            for (int j = 0; j < 4; j++) {
                unsigned hh, ll; split_tf32(kvl[j], hh, ll);
                *reinterpret_cast<float2*>(Ks + kbase + j * 4) =
                    make_float2(__uint_as_float(hh), __uint_as_float(ll));
            }
            float4 v4 = *reinterpret_cast<const float4*>(V + (size_t)(kv0 + r) * DKH + c4);
            float vvl[4] = { v4.x, v4.y, v4.z, v4.w };
            int vq = qperm(r);
#pragma unroll
            for (int j = 0; j < 4; j++) {
                unsigned hh, ll; split_tf32(vvl[j], hh, ll);
                *reinterpret_cast<float2*>(Vt + (c4 + j) * LDV + vq) =
                    make_float2(__uint_as_float(hh), __uint_as_float(ll));
            }
        }
        __syncthreads();

        // ---- S = Q K^T (TF32x3; scale folded into Q) ----
        float s[8][4];
#pragma unroll
        for (int i = 0; i < 8; i++)
#pragma unroll
            for (int j = 0; j < 4; j++) s[i][j] = 0.f;

#pragma unroll
        for (int ks = 0; ks < 8; ks++) {
            const int fofs = ks * 16 + lq * 4;
#pragma unroll
            for (int nt = 0; nt < 8; nt++) {
                int nb = nt * 8 + r8;
                float4 f = *reinterpret_cast<const float4*>(Ks + nb * LDK + fofs);
                unsigned bhv[2] = { __float_as_uint(f.x), __float_as_uint(f.z) };
                unsigned blv[2] = { __float_as_uint(f.y), __float_as_uint(f.w) };
                mma8(s[nt], qhi[ks], bhv);
                mma8(s[nt], qhi[ks], blv);
                mma8(s[nt], qlo[ks], bhv);
            }
        }

        // ---- causal mask on diagonal tile ----
        if (maskv && t == qt) {
            int rg0 = q0 + rl;
#pragma unroll
            for (int nt = 0; nt < 8; nt++) {
                int cg = kv0 + nt * 8 + lq * 2;
                if (cg > rg0)         s[nt][0] = -1e30f;
                if (cg + 1 > rg0)     s[nt][1] = -1e30f;
                if (cg > rg0 + 8)     s[nt][2] = -1e30f;
                if (cg + 1 > rg0 + 8) s[nt][3] = -1e30f;
            }
        }

        // ---- online softmax (base 2) ----
#pragma unroll
        for (int sub = 0; sub < 2; sub++) {
            float tm = -1e30f;
#pragma unroll
            for (int nt = 0; nt < 8; nt++)
                tm = fmaxf(tm, fmaxf(s[nt][2 * sub], s[nt][2 * sub + 1]));
            tm = fmaxf(tm, __shfl_xor_sync(0xffffffffu, tm, 1));
            tm = fmaxf(tm, __shfl_xor_sync(0xffffffffu, tm, 2));
            float mn = fmaxf(m[sub], tm);
            float alpha = exp2f(m[sub] - mn);
            float rs = 0.f;
#pragma unroll
            for (int nt = 0; nt < 8; nt++) {
                float p0 = exp2f(s[nt][2 * sub] - mn);
                float p1 = exp2f(s[nt][2 * sub + 1] - mn);
                s[nt][2 * sub] = p0; s[nt][2 * sub + 1] = p1;
                rs += p0 + p1;
            }
            rs += __shfl_xor_sync(0xffffffffu, rs, 1);
            rs += __shfl_xor_sync(0xffffffffu, rs, 2);
            l[sub] = l[sub] * alpha + rs;
            m[sub] = mn;
#pragma unroll
            for (int dt = 0; dt < 8; dt++) {
                o[dt][2 * sub]     *= alpha;
                o[dt][2 * sub + 1] *= alpha;
            }
        }

        // ---- store P (tf32-rounded) to SMEM, pair-permuted ----
#pragma unroll
        for (int nt = 0; nt < 8; nt++) {
            int cl0 = lq * 2;                       // local col within nt-tile (0..7)
            int p0 = nt * 8 + (cl0 & 3) * 2 + (cl0 >> 2);
            int p1 = nt * 8 + ((cl0 + 1) & 3) * 2 + ((cl0 + 1) >> 2);
            Ps[rl * LDP + p0]       = __uint_as_float(f2tf(s[nt][0]));
            Ps[rl * LDP + p1]       = __uint_as_float(f2tf(s[nt][1]));
            Ps[(rl + 8) * LDP + p0] = __uint_as_float(f2tf(s[nt][2]));
            Ps[(rl + 8) * LDP + p1] = __uint_as_float(f2tf(s[nt][3]));
        }
        __syncthreads();

        // ---- O += P * V (P single tf32, V hi+lo), skip masked k-tiles ----
        int ksmax = (maskv && t == qt) ? (2 * warp + 2) : 8;
#pragma unroll
        for (int ks = 0; ks < 8; ks++) {
            if (ks >= ksmax) break;
            float2 u0 = *reinterpret_cast<const float2*>(Ps + rl * LDP + ks * 8 + lq * 2);
            float2 u1 = *reinterpret_cast<const float2*>(Ps + (rl + 8) * LDP + ks * 8 + lq * 2);
            unsigned pa[4] = { __float_as_uint(u0.x), __float_as_uint(u1.x),
                               __float_as_uint(u0.y), __float_as_uint(u1.y) };
            const int fofs = ks * 16 + lq * 4;
#pragma unroll
            for (int dt = 0; dt < 8; dt++) {
                int db = dt * 8 + r8;
                float4 f = *reinterpret_cast<const float4*>(Vt + db * LDV + fofs);
                unsigned bhv[2] = { __float_as_uint(f.x), __float_as_uint(f.z) };
                unsigned blv[2] = { __float_as_uint(f.y), __float_as_uint(f.w) };
                mma8(o[dt], pa, bhv);
                mma8(o[dt], pa, blv);
            }
        }
        __syncthreads();
    }

    // ---- epilogue: attn[b, q, h, d] = O / l ----
    float i0 = 1.f / l[0];
    float i1 = 1.f / l[1];
    int rg = q0 + rl;
    size_t ob  = (((size_t)b * SEQL + rg) * NHEAD + h) * DKH;
    size_t ob2 = (((size_t)b * SEQL + rg + 8) * NHEAD + h) * DKH;
#pragma unroll
    for (int dt = 0; dt < 8; dt++) {
        int c = dt * 8 + lq * 2;
        g_attn[ob + c]      = o[dt][0] * i0;
        g_attn[ob + c + 1]  = o[dt][1] * i0;
        g_attn[ob2 + c]     = o[dt][2] * i1;
        g_attn[ob2 + c + 1] = o[dt][3] * i1;
    }
}

// ---------------- launcher ---------------------------------------------------
extern "C" void kernel_launch(void* const* d_in, const int* in_sizes, int n_in,
                              void* d_out, int out_size)
{
    const float* x_q = (const float*)d_in[0];
    const float* x_k = (const float*)d_in[1];
    const float* x_v = (const float*)d_in[2];
    const float* w_q = (const float*)d_in[3];
    const float* w_k = (const float*)d_in[4];
    const float* w_v = (const float*)d_in[5];
    const float* w_o = (const float*)d_in[6];
    const int*   msk = (const int*)d_in[7];
    float* out = (float*)d_out;

    cudaFuncSetAttribute((const void*)gemm_x3_kernel<0,3>, cudaFuncAttributeMaxDynamicSharedMemorySize, GSM_BYTES);
    cudaFuncSetAttribute((const void*)gemm_x3_kernel<0,2>, cudaFuncAttributeMaxDynamicSharedMemorySize, GSM_BYTES);
    cudaFuncSetAttribute((const void*)gemm_x3_kernel<1,2>, cudaFuncAttributeMaxDynamicSharedMemorySize, GSM_BYTES);
    cudaFuncSetAttribute((const void*)flash_kernel, cudaFuncAttributeMaxDynamicSharedMemorySize, FSM_BYTES);

    // Q, K projections: TF32x3 (feed the score path)
    gemm_x3_kernel<0,3><<<dim3(MROWS / 128, NHEAD, 2), 256, GSM_BYTES>>>(
        x_q, x_k, x_v, w_q, w_k, w_v, nullptr, 0);
    // V projection: TF32x2
    gemm_x3_kernel<0,2><<<dim3(MROWS / 128, NHEAD, 1), 256, GSM_BYTES>>>(
        x_q, x_k, x_v, w_q, w_k, w_v, nullptr, 2);

    flash_kernel<<<dim3(SEQL / 64, BATCHN * NHEAD), 128, FSM_BYTES>>>(msk);

    // Output projection: TF32x2
    gemm_x3_kernel<1,2><<<dim3(MROWS / 128, EMB / 64, 1), 256, GSM_BYTES>>>(
        nullptr, nullptr, nullptr, w_o, nullptr, nullptr, out, 0);
}

// round 4
// speedup vs baseline: 1.8165x; 1.8165x over previous
#include <cuda_runtime.h>
#include <cstdint>

#define BATCHN 4
#define SEQL   2048
#define EMB    1024
#define NHEAD  16
#define DKH    64
#define MROWS  (BATCHN*SEQL)   /* 8192 */

// ---------------- scratch (static device globals; no runtime allocation) ----
__device__ float g_q[(size_t)BATCHN*NHEAD*SEQL*DKH];     // [b,h,s,d]
__device__ float g_k[(size_t)BATCHN*NHEAD*SEQL*DKH];
__device__ float g_v[(size_t)BATCHN*NHEAD*SEQL*DKH];
__device__ float g_attn[(size_t)MROWS*EMB];              // [b,s,h*d]

// ---------------- helpers ---------------------------------------------------
__device__ __forceinline__ unsigned f2tf(float x) {
    unsigned r;
    asm("cvt.rna.tf32.f32 %0, %1;" : "=r"(r) : "f"(x));
    return r;
}
__device__ __forceinline__ void split_tf32(float x, unsigned &hi, unsigned &lo) {
    hi = f2tf(x);
    lo = f2tf(x - __uint_as_float(hi));
}
// split a float4 into two smem float4s {h0,l0,h1,l1},{h2,l2,h3,l3}
__device__ __forceinline__ void split_store2(float* dst, float4 v) {
    unsigned h0,l0,h1,l1,h2,l2,h3,l3;
    split_tf32(v.x,h0,l0); split_tf32(v.y,h1,l1);
    split_tf32(v.z,h2,l2); split_tf32(v.w,h3,l3);
    reinterpret_cast<float4*>(dst)[0] = make_float4(__uint_as_float(h0), __uint_as_float(l0),
                                                    __uint_as_float(h1), __uint_as_float(l1));
    reinterpret_cast<float4*>(dst)[1] = make_float4(__uint_as_float(h2), __uint_as_float(l2),
                                                    __uint_as_float(h3), __uint_as_float(l3));
}
__device__ __forceinline__ void mma8(float c[4], const unsigned a[4], const unsigned b[2]) {
    asm volatile(
        "mma.sync.aligned.m16n8k8.row.col.f32.tf32.tf32.f32 "
        "{%0,%1,%2,%3},{%4,%5,%6,%7},{%8,%9},{%0,%1,%2,%3};\n"
        : "+f"(c[0]), "+f"(c[1]), "+f"(c[2]), "+f"(c[3])
        : "f"(__uint_as_float(a[0])) /*dummy to keep types*/, "r"(a[1]), "r"(a[2]), "r"(a[3]), "r"(b[0]), "r"(b[1]));
}
// NOTE: the dummy above would be wrong — define properly:
__device__ __forceinline__ void mma8u(float c[4], unsigned a0, unsigned a1, unsigned a2, unsigned a3,
                                      unsigned b0, unsigned b1) {
    asm volatile(
        "mma.sync.aligned.m16n8k8.row.col.f32.tf32.tf32.f32 "
        "{%0,%1,%2,%3},{%4,%5,%6,%7},{%8,%9},{%0,%1,%2,%3};\n"
        : "+f"(c[0]), "+f"(c[1]), "+f"(c[2]), "+f"(c[3])
        : "r"(a0), "r"(a1), "r"(a2), "r"(a3), "r"(b0), "r"(b1));
}

// ---------------- GEMM (TF32 split, adjacent hi/lo interleave) --------------
// A tile: [m 0..127][2k+hl], LDA=72 words.  B tile: [k 0..31][2n+hl], LDB=136.
// MODE 0: per-head projections (sel = blockIdx.z + selbase -> q/k/v).
// MODE 1: output projection. A = g_attn, B = w_o, C = Cext.
#define LDA 72
#define LDB 136
#define GSM_FLOATS (128*LDA + 32*LDB)
#define GSM_BYTES  (GSM_FLOATS*4)

template<int MODE, int PASSES>
__global__ void __launch_bounds__(256) gemm_x3_kernel(
    const float* __restrict__ A0, const float* __restrict__ A1, const float* __restrict__ A2,
    const float* __restrict__ B0, const float* __restrict__ B1, const float* __restrict__ B2,
    float* __restrict__ Cext, int selbase)
{
    extern __shared__ float sm[];
    float* As = sm;              // [128][LDA]
    float* Bs = sm + 128 * LDA;  // [32][LDB]

    const int tid  = threadIdx.x;
    const int lane = tid & 31;
    const int warp = tid >> 5;
    const int wm = warp >> 1, wn = warp & 1;
    const int r8 = lane >> 2, lq = lane & 3;
    const int row0 = blockIdx.x * 128;

    const float* A;
    const float* Bt;
    int ldb, n0;
    float* Cq;
    if (MODE == 0) {
        int sel = blockIdx.z + selbase;
        A = sel == 0 ? A0 : (sel == 1 ? A1 : A2);
        const float* W = sel == 0 ? B0 : (sel == 1 ? B1 : B2);
        Bt = W + (size_t)blockIdx.y * EMB * 64; ldb = 64; n0 = 0;
        Cq = sel == 0 ? g_q : (sel == 1 ? g_k : g_v);
    } else {
        A = g_attn; Bt = B0; ldb = EMB; n0 = blockIdx.y * 64; Cq = Cext;
    }

    float acc[2][4][4];
#pragma unroll
    for (int i = 0; i < 2; i++)
#pragma unroll
        for (int j = 0; j < 4; j++)
#pragma unroll
            for (int r = 0; r < 4; r++) acc[i][j][r] = 0.f;

    float4 ra[4], rb[2];
    // prologue load (k0 = 0)
#pragma unroll
    for (int ii = 0; ii < 4; ii++) {
        int i = tid + ii * 256; int r = i >> 3, c4 = (i & 7) << 2;
        ra[ii] = *reinterpret_cast<const float4*>(A + (size_t)(row0 + r) * EMB + c4);
    }
#pragma unroll
    for (int ii = 0; ii < 2; ii++) {
        int i = tid + ii * 256; int r = i >> 4, c4 = (i & 15) << 2;
        rb[ii] = *reinterpret_cast<const float4*>(Bt + (size_t)r * ldb + n0 + c4);
    }

    for (int k0 = 0; k0 < EMB; k0 += 32) {
        // ---- split + store current tile ----
#pragma unroll
        for (int ii = 0; ii < 4; ii++) {
            int i = tid + ii * 256; int r = i >> 3, c4 = (i & 7) << 2;
            split_store2(As + r * LDA + 2 * c4, ra[ii]);
        }
#pragma unroll
        for (int ii = 0; ii < 2; ii++) {
            int i = tid + ii * 256; int r = i >> 4, c4 = (i & 15) << 2;
            split_store2(Bs + r * LDB + 2 * c4, rb[ii]);
        }
        __syncthreads();

        // ---- prefetch next tile into regs ----
        if (k0 + 32 < EMB) {
#pragma unroll
            for (int ii = 0; ii < 4; ii++) {
                int i = tid + ii * 256; int r = i >> 3, c4 = (i & 7) << 2;
                ra[ii] = *reinterpret_cast<const float4*>(A + (size_t)(row0 + r) * EMB + k0 + 32 + c4);
            }
#pragma unroll
            for (int ii = 0; ii < 2; ii++) {
                int i = tid + ii * 256; int r = i >> 4, c4 = (i & 15) << 2;
                rb[ii] = *reinterpret_cast<const float4*>(Bt + (size_t)(k0 + 32 + r) * ldb + n0 + c4);
            }
        }

        // ---- compute ----
#pragma unroll
        for (int ks = 0; ks < 4; ks++) {
            const int kk = ks * 8;
            unsigned ah[2][4], al[2][4];
#pragma unroll
            for (int mt = 0; mt < 2; mt++) {
                int rbse = wm * 32 + mt * 16 + r8;
                float2 f0 = *reinterpret_cast<const float2*>(As + rbse * LDA + 2 * (kk + lq));
                float2 f1 = *reinterpret_cast<const float2*>(As + (rbse + 8) * LDA + 2 * (kk + lq));
                float2 f2 = *reinterpret_cast<const float2*>(As + rbse * LDA + 2 * (kk + 4 + lq));
                float2 f3 = *reinterpret_cast<const float2*>(As + (rbse + 8) * LDA + 2 * (kk + 4 + lq));
                ah[mt][0] = __float_as_uint(f0.x); al[mt][0] = __float_as_uint(f0.y);
                ah[mt][1] = __float_as_uint(f1.x); al[mt][1] = __float_as_uint(f1.y);
                ah[mt][2] = __float_as_uint(f2.x); al[mt][2] = __float_as_uint(f2.y);
                ah[mt][3] = __float_as_uint(f3.x); al[mt][3] = __float_as_uint(f3.y);
            }
            unsigned bh[4][2], bl[4][2];
#pragma unroll
            for (int nt = 0; nt < 4; nt++) {
                int nb = wn * 32 + nt * 8 + r8;
                float2 g0 = *reinterpret_cast<const float2*>(Bs + (kk + lq) * LDB + 2 * nb);
                float2 g1 = *reinterpret_cast<const float2*>(Bs + (kk + 4 + lq) * LDB + 2 * nb);
                bh[nt][0] = __float_as_uint(g0.x); bl[nt][0] = __float_as_uint(g0.y);
                bh[nt][1] = __float_as_uint(g1.x); bl[nt][1] = __float_as_uint(g1.y);
            }
#pragma unroll
            for (int mt = 0; mt < 2; mt++)
#pragma unroll
                for (int nt = 0; nt < 4; nt++) {
                    mma8u(acc[mt][nt], ah[mt][0], ah[mt][1], ah[mt][2], ah[mt][3], bh[nt][0], bh[nt][1]);
                    if (PASSES >= 2)
                        mma8u(acc[mt][nt], al[mt][0], al[mt][1], al[mt][2], al[mt][3], bh[nt][0], bh[nt][1]);
                    if (PASSES >= 3)
                        mma8u(acc[mt][nt], ah[mt][0], ah[mt][1], ah[mt][2], ah[mt][3], bl[nt][0], bl[nt][1]);
                }
        }
        __syncthreads();
    }

    // ---- epilogue ----
#pragma unroll
    for (int mt = 0; mt < 2; mt++) {
        int r = row0 + wm * 32 + mt * 16 + r8;
#pragma unroll
        for (int nt = 0; nt < 4; nt++) {
            int c = wn * 32 + nt * 8 + lq * 2;
            if (MODE == 0) {
                int b = r >> 11, s = r & 2047;
                size_t base  = (((size_t)b * NHEAD + blockIdx.y) * SEQL + s) * DKH;
                size_t base2 = base + (size_t)8 * DKH;
                Cq[base + c]      = acc[mt][nt][0];
                Cq[base + c + 1]  = acc[mt][nt][1];
                Cq[base2 + c]     = acc[mt][nt][2];
                Cq[base2 + c + 1] = acc[mt][nt][3];
            } else {
                size_t base = (size_t)r * EMB + blockIdx.y * 64 + c;
                Cq[base]               = acc[mt][nt][0];
                Cq[base + 1]           = acc[mt][nt][1];
                Cq[base + 8 * EMB]     = acc[mt][nt][2];
                Cq[base + 8 * EMB + 1] = acc[mt][nt][3];
            }
        }
    }
}

// ---------------- flash attention (causal) ----------------------------------
// K tile: [kv 0..63][2d+hl] LDK=136.  V tile: [kv 0..63][2d+hl] LDV=136.
// P/Q tile: [row 0..63][col], LDP=68 (single precision tf32 values).
#define LDK 136
#define LDV 136
#define LDP 68
#define F_K 0
#define F_V (64*LDK)
#define F_P (64*LDK + 64*LDV)
#define FSM_FLOATS (64*LDK + 64*LDV + 64*LDP)
#define FSM_BYTES  (FSM_FLOATS*4)
#define LOG2E 1.4426950408889634f

__global__ void __launch_bounds__(128) flash_kernel(const int* __restrict__ maskp)
{
    extern __shared__ float sm[];
    float* Ks = sm + F_K;
    float* Vs = sm + F_V;
    float* Ps = sm + F_P;

    const int tid  = threadIdx.x;
    const int lane = tid & 31;
    const int warp = tid >> 5;
    const int r8 = lane >> 2, lq = lane & 3;
    const int qt = blockIdx.x;
    const int bh = blockIdx.y;
    const int b = bh >> 4, h = bh & 15;
    const int q0 = qt * 64;

    const float* Q = g_q + (size_t)bh * SEQL * DKH;
    const float* K = g_k + (size_t)bh * SEQL * DKH;
    const float* V = g_v + (size_t)bh * SEQL * DKH;

    // ---- stage Q tile scaled by 8*log2(e) into Ps ----
    const float qscale = 8.f * LOG2E;
#pragma unroll
    for (int ii = 0; ii < 8; ii++) {
        int i = tid + ii * 128;
        int r = i >> 4, c4 = (i & 15) << 2;
        float4 v4 = *reinterpret_cast<const float4*>(Q + (size_t)(q0 + r) * DKH + c4);
        float* d = Ps + r * LDP + c4;
        d[0] = v4.x * qscale; d[1] = v4.y * qscale; d[2] = v4.z * qscale; d[3] = v4.w * qscale;
    }
    __syncthreads();

    const int rl = warp * 16 + r8;
    unsigned qhi[8][4], qlo[8][4];
#pragma unroll
    for (int ks = 0; ks < 8; ks++) {
        split_tf32(Ps[rl * LDP + ks * 8 + lq],           qhi[ks][0], qlo[ks][0]);
        split_tf32(Ps[(rl + 8) * LDP + ks * 8 + lq],     qhi[ks][1], qlo[ks][1]);
        split_tf32(Ps[rl * LDP + ks * 8 + 4 + lq],       qhi[ks][2], qlo[ks][2]);
        split_tf32(Ps[(rl + 8) * LDP + ks * 8 + 4 + lq], qhi[ks][3], qlo[ks][3]);
    }

    float m[2] = { -1e30f, -1e30f };
    float l[2] = { 0.f, 0.f };
    float o[8][4];
#pragma unroll
    for (int i = 0; i < 8; i++)
#pragma unroll
        for (int j = 0; j < 4; j++) o[i][j] = 0.f;

    const int maskv = maskp[0];
    const int ntiles = maskv ? (qt + 1) : (SEQL / 64);

    for (int t = 0; t < ntiles; t++) {
        const int kv0 = t * 64;
        // ---- cooperative K / V load with split + interleaved store ----
#pragma unroll
        for (int ii = 0; ii < 8; ii++) {
            int i = tid + ii * 128;
            int r = i >> 4, c4 = (i & 15) << 2;
            float4 k4 = *reinterpret_cast<const float4*>(K + (size_t)(kv0 + r) * DKH + c4);
            split_store2(Ks + r * LDK + 2 * c4, k4);
            float4 v4 = *reinterpret_cast<const float4*>(V + (size_t)(kv0 + r) * DKH + c4);
            split_store2(Vs + r * LDV + 2 * c4, v4);
        }
        __syncthreads();

        // ---- S = Q K^T (TF32x3; scale folded into Q) ----
        float s[8][4];
#pragma unroll
        for (int i = 0; i < 8; i++)
#pragma unroll
            for (int j = 0; j < 4; j++) s[i][j] = 0.f;

#pragma unroll
        for (int ks = 0; ks < 8; ks++) {
            const int kk = ks * 8;
#pragma unroll
            for (int nt = 0; nt < 8; nt++) {
                int nb = nt * 8 + r8;     // kv index (B n-dim)
                float2 f0 = *reinterpret_cast<const float2*>(Ks + nb * LDK + 2 * (kk + lq));
                float2 f1 = *reinterpret_cast<const float2*>(Ks + nb * LDK + 2 * (kk + 4 + lq));
                unsigned bh0 = __float_as_uint(f0.x), bl0 = __float_as_uint(f0.y);
                unsigned bh1 = __float_as_uint(f1.x), bl1 = __float_as_uint(f1.y);
                mma8u(s[nt], qhi[ks][0], qhi[ks][1], qhi[ks][2], qhi[ks][3], bh0, bh1);
                mma8u(s[nt], qhi[ks][0], qhi[ks][1], qhi[ks][2], qhi[ks][3], bl0, bl1);
                mma8u(s[nt], qlo[ks][0], qlo[ks][1], qlo[ks][2], qlo[ks][3], bh0, bh1);
            }
        }

        // ---- causal mask on diagonal tile ----
        if (maskv && t == qt) {
            int rg0 = q0 + rl;
#pragma unroll
            for (int nt = 0; nt < 8; nt++) {
                int cg = kv0 + nt * 8 + lq * 2;
                if (cg > rg0)         s[nt][0] = -1e30f;
                if (cg + 1 > rg0)     s[nt][1] = -1e30f;
                if (cg > rg0 + 8)     s[nt][2] = -1e30f;
                if (cg + 1 > rg0 + 8) s[nt][3] = -1e30f;
            }
        }

        // ---- online softmax (base 2) ----
#pragma unroll
        for (int sub = 0; sub < 2; sub++) {
            float tm = -1e30f;
#pragma unroll
            for (int nt = 0; nt < 8; nt++)
                tm = fmaxf(tm, fmaxf(s[nt][2 * sub], s[nt][2 * sub + 1]));
            tm = fmaxf(tm, __shfl_xor_sync(0xffffffffu, tm, 1));
            tm = fmaxf(tm, __shfl_xor_sync(0xffffffffu, tm, 2));
            float mn = fmaxf(m[sub], tm);
            float alpha = exp2f(m[sub] - mn);
            float rs = 0.f;
#pragma unroll
            for (int nt = 0; nt < 8; nt++) {
                float p0 = exp2f(s[nt][2 * sub] - mn);
                float p1 = exp2f(s[nt][2 * sub + 1] - mn);
                s[nt][2 * sub] = p0; s[nt][2 * sub + 1] = p1;
                rs += p0 + p1;
            }
            rs += __shfl_xor_sync(0xffffffffu, rs, 1);
            rs += __shfl_xor_sync(0xffffffffu, rs, 2);
            l[sub] = l[sub] * alpha + rs;
            m[sub] = mn;
#pragma unroll
            for (int dt = 0; dt < 8; dt++) {
                o[dt][2 * sub]     *= alpha;
                o[dt][2 * sub + 1] *= alpha;
            }
        }

        // ---- store P (tf32-rounded) to SMEM ----
#pragma unroll
        for (int nt = 0; nt < 8; nt++) {
            int c = nt * 8 + lq * 2;
            *reinterpret_cast<float2*>(Ps + rl * LDP + c) =
                make_float2(__uint_as_float(f2tf(s[nt][0])), __uint_as_float(f2tf(s[nt][1])));
            *reinterpret_cast<float2*>(Ps + (rl + 8) * LDP + c) =
                make_float2(__uint_as_float(f2tf(s[nt][2])), __uint_as_float(f2tf(s[nt][3])));
        }
        __syncthreads();

        // ---- O += P * V (P single tf32, V hi+lo), skip fully-masked k-tiles ----
        int ksmax = (maskv && t == qt) ? (2 * warp + 2) : 8;
#pragma unroll
        for (int ks = 0; ks < 8; ks++) {
            if (ks >= ksmax) break;
            int kkk = ks * 8 + lq;
            unsigned pa0 = __float_as_uint(Ps[rl * LDP + kkk]);
            unsigned pa1 = __float_as_uint(Ps[(rl + 8) * LDP + kkk]);
            unsigned pa2 = __float_as_uint(Ps[rl * LDP + kkk + 4]);
            unsigned pa3 = __float_as_uint(Ps[(rl + 8) * LDP + kkk + 4]);
#pragma unroll
            for (int dt = 0; dt < 8; dt++) {
                int db = dt * 8 + r8;     // d index (B n-dim)
                float2 g0 = *reinterpret_cast<const float2*>(Vs + (ks * 8 + lq) * LDV + 2 * db);
                float2 g1 = *reinterpret_cast<const float2*>(Vs + (ks * 8 + 4 + lq) * LDV + 2 * db);
                unsigned bh0 = __float_as_uint(g0.x), bl0 = __float_as_uint(g0.y);
                unsigned bh1 = __float_as_uint(g1.x), bl1 = __float_as_uint(g1.y);
                mma8u(o[dt], pa0, pa1, pa2, pa3, bh0, bh1);
                mma8u(o[dt], pa0, pa1, pa2, pa3, bl0, bl1);
            }
        }
        __syncthreads();
    }

    // ---- epilogue: attn[b, q, h, d] = O / l ----
    float i0 = 1.f / l[0];
    float i1 = 1.f / l[1];
    int rg = q0 + rl;
    size_t ob  = (((size_t)b * SEQL + rg) * NHEAD + h) * DKH;
    size_t ob2 = (((size_t)b * SEQL + rg + 8) * NHEAD + h) * DKH;
#pragma unroll
    for (int dt = 0; dt < 8; dt++) {
        int c = dt * 8 + lq * 2;
        g_attn[ob + c]      = o[dt][0] * i0;
        g_attn[ob + c + 1]  = o[dt][1] * i0;
        g_attn[ob2 + c]     = o[dt][2] * i1;
        g_attn[ob2 + c + 1] = o[dt][3] * i1;
    }
}

// ---------------- launcher ---------------------------------------------------
extern "C" void kernel_launch(void* const* d_in, const int* in_sizes, int n_in,
                              void* d_out, int out_size)
{
    const float* x_q = (const float*)d_in[0];
    const float* x_k = (const float*)d_in[1];
    const float* x_v = (const float*)d_in[2];
    const float* w_q = (const float*)d_in[3];
    const float* w_k = (const float*)d_in[4];
    const float* w_v = (const float*)d_in[5];
    const float* w_o = (const float*)d_in[6];
    const int*   msk = (const int*)d_in[7];
    float* out = (float*)d_out;

    cudaFuncSetAttribute((const void*)gemm_x3_kernel<0,3>, cudaFuncAttributeMaxDynamicSharedMemorySize, GSM_BYTES);
    cudaFuncSetAttribute((const void*)gemm_x3_kernel<0,2>, cudaFuncAttributeMaxDynamicSharedMemorySize, GSM_BYTES);
    cudaFuncSetAttribute((const void*)gemm_x3_kernel<1,2>, cudaFuncAttributeMaxDynamicSharedMemorySize, GSM_BYTES);
    cudaFuncSetAttribute((const void*)flash_kernel, cudaFuncAttributeMaxDynamicSharedMemorySize, FSM_BYTES);

    // Q, K projections: TF32x3 (feed the score path)
    gemm_x3_kernel<0,3><<<dim3(MROWS / 128, NHEAD, 2), 256, GSM_BYTES>>>(
        x_q, x_k, x_v, w_q, w_k, w_v, nullptr, 0);
    // V projection: TF32x2
    gemm_x3_kernel<0,2><<<dim3(MROWS / 128, NHEAD, 1), 256, GSM_BYTES>>>(
        x_q, x_k, x_v, w_q, w_k, w_v, nullptr, 2);

    flash_kernel<<<dim3(SEQL / 64, BATCHN * NHEAD), 128, FSM_BYTES>>>(msk);

    // Output projection: TF32x2
    gemm_x3_kernel<1,2><<<dim3(MROWS / 128, EMB / 64, 1), 256, GSM_BYTES>>>(
        nullptr, nullptr, nullptr, w_o, nullptr, nullptr, out, 0);
}

// round 6
// speedup vs baseline: 2.2316x; 1.2285x over previous
#include <cuda_runtime.h>
#include <cstdint>

#define BATCHN 4
#define SEQL   2048
#define EMB    1024
#define NHEAD  16
#define DKH    64
#define MROWS  (BATCHN*SEQL)   /* 8192 */

// ---------------- scratch (static device globals; no runtime allocation) ----
__device__ float g_q[(size_t)BATCHN*NHEAD*SEQL*DKH];     // [b,h,s,d]
__device__ float g_k[(size_t)BATCHN*NHEAD*SEQL*DKH];
__device__ float g_v[(size_t)BATCHN*NHEAD*SEQL*DKH];
__device__ float g_attn[(size_t)MROWS*EMB];              // [b,s,h*d]

// ---------------- helpers ---------------------------------------------------
__device__ __forceinline__ unsigned f2tf(float x) {
    unsigned r;
    asm("cvt.rna.tf32.f32 %0, %1;" : "=r"(r) : "f"(x));
    return r;
}
__device__ __forceinline__ void split_tf32(float x, unsigned &hi, unsigned &lo) {
    hi = f2tf(x);
    lo = f2tf(x - __uint_as_float(hi));
}
__device__ __forceinline__ void mma8u(float c[4], unsigned a0, unsigned a1, unsigned a2, unsigned a3,
                                      unsigned b0, unsigned b1) {
    asm volatile(
        "mma.sync.aligned.m16n8k8.row.col.f32.tf32.tf32.f32 "
        "{%0,%1,%2,%3},{%4,%5,%6,%7},{%8,%9},{%0,%1,%2,%3};\n"
        : "+f"(c[0]), "+f"(c[1]), "+f"(c[2]), "+f"(c[3])
        : "r"(a0), "r"(a1), "r"(a2), "r"(a3), "r"(b0), "r"(b1));
}

// ---------------- GEMM (TF32 split), R2 layout + PASSES template ------------
// MODE 0: per-head projections. sel = blockIdx.z + selbase -> q/k/v.
// MODE 1: output projection. A = g_attn, B = w_o, C = Cext.
#define GA_LD 36
#define GB_LD 72
#define GSM_FLOATS (2*128*GA_LD + 2*32*GB_LD)
#define GSM_BYTES  (GSM_FLOATS*4)

template<int MODE, int PASSES>
__global__ void __launch_bounds__(256) gemm_x3_kernel(
    const float* __restrict__ A0, const float* __restrict__ A1, const float* __restrict__ A2,
    const float* __restrict__ B0, const float* __restrict__ B1, const float* __restrict__ B2,
    float* __restrict__ Cext, int selbase)
{
    extern __shared__ float sm[];
    float* Ah = sm;
    float* Al = Ah + 128 * GA_LD;
    float* Bh = Al + 128 * GA_LD;
    float* Bl = Bh + 32 * GB_LD;

    const int tid  = threadIdx.x;
    const int lane = tid & 31;
    const int warp = tid >> 5;
    const int wm = warp >> 1, wn = warp & 1;
    const int r8 = lane >> 2, lq = lane & 3;
    const int row0 = blockIdx.x * 128;

    const float* A;
    const float* Bt;
    int ldb, n0;
    float* Cq;
    if (MODE == 0) {
        int sel = blockIdx.z + selbase;
        A = sel == 0 ? A0 : (sel == 1 ? A1 : A2);
        const float* W = sel == 0 ? B0 : (sel == 1 ? B1 : B2);
        Bt = W + (size_t)blockIdx.y * EMB * 64; ldb = 64; n0 = 0;
        Cq = sel == 0 ? g_q : (sel == 1 ? g_k : g_v);
    } else {
        A = g_attn; Bt = B0; ldb = EMB; n0 = blockIdx.y * 64; Cq = Cext;
    }

    float acc[2][4][4];
#pragma unroll
    for (int i = 0; i < 2; i++)
#pragma unroll
        for (int j = 0; j < 4; j++)
#pragma unroll
            for (int r = 0; r < 4; r++) acc[i][j][r] = 0.f;

    float4 ra[4], rb[2];
    // prologue load (k0 = 0)
#pragma unroll
    for (int ii = 0; ii < 4; ii++) {
        int i = tid + ii * 256; int r = i >> 3, c4 = (i & 7) << 2;
        ra[ii] = *reinterpret_cast<const float4*>(A + (size_t)(row0 + r) * EMB + c4);
    }
#pragma unroll
    for (int ii = 0; ii < 2; ii++) {
        int i = tid + ii * 256; int r = i >> 4, c4 = (i & 15) << 2;
        rb[ii] = *reinterpret_cast<const float4*>(Bt + (size_t)r * ldb + n0 + c4);
    }

    for (int k0 = 0; k0 < EMB; k0 += 32) {
        // ---- split + store current tile ----
#pragma unroll
        for (int ii = 0; ii < 4; ii++) {
            int i = tid + ii * 256; int r = i >> 3, c4 = (i & 7) << 2;
            float v[4] = { ra[ii].x, ra[ii].y, ra[ii].z, ra[ii].w };
#pragma unroll
            for (int j = 0; j < 4; j++) {
                unsigned h, l; split_tf32(v[j], h, l);
                Ah[r * GA_LD + c4 + j] = __uint_as_float(h);
                Al[r * GA_LD + c4 + j] = __uint_as_float(l);
            }
        }
#pragma unroll
        for (int ii = 0; ii < 2; ii++) {
            int i = tid + ii * 256; int r = i >> 4, c4 = (i & 15) << 2;
            float v[4] = { rb[ii].x, rb[ii].y, rb[ii].z, rb[ii].w };
#pragma unroll
            for (int j = 0; j < 4; j++) {
                unsigned h, l; split_tf32(v[j], h, l);
                Bh[r * GB_LD + c4 + j] = __uint_as_float(h);
                if (PASSES >= 3) Bl[r * GB_LD + c4 + j] = __uint_as_float(l);
            }
        }
        __syncthreads();

        // ---- prefetch next tile into regs ----
        if (k0 + 32 < EMB) {
#pragma unroll
            for (int ii = 0; ii < 4; ii++) {
                int i = tid + ii * 256; int r = i >> 3, c4 = (i & 7) << 2;
                ra[ii] = *reinterpret_cast<const float4*>(A + (size_t)(row0 + r) * EMB + k0 + 32 + c4);
            }
#pragma unroll
            for (int ii = 0; ii < 2; ii++) {
                int i = tid + ii * 256; int r = i >> 4, c4 = (i & 15) << 2;
                rb[ii] = *reinterpret_cast<const float4*>(Bt + (size_t)(k0 + 32 + r) * ldb + n0 + c4);
            }
        }

        // ---- compute ----
#pragma unroll
        for (int ks = 0; ks < 4; ks++) {
            const int kk = ks * 8;
            unsigned ah[2][4], al[2][4];
#pragma unroll
            for (int mt = 0; mt < 2; mt++) {
                int rbse = wm * 32 + mt * 16 + r8;
                ah[mt][0] = __float_as_uint(Ah[rbse * GA_LD + kk + lq]);
                ah[mt][1] = __float_as_uint(Ah[(rbse + 8) * GA_LD + kk + lq]);
                ah[mt][2] = __float_as_uint(Ah[rbse * GA_LD + kk + 4 + lq]);
                ah[mt][3] = __float_as_uint(Ah[(rbse + 8) * GA_LD + kk + 4 + lq]);
                al[mt][0] = __float_as_uint(Al[rbse * GA_LD + kk + lq]);
                al[mt][1] = __float_as_uint(Al[(rbse + 8) * GA_LD + kk + lq]);
                al[mt][2] = __float_as_uint(Al[rbse * GA_LD + kk + 4 + lq]);
                al[mt][3] = __float_as_uint(Al[(rbse + 8) * GA_LD + kk + 4 + lq]);
            }
            unsigned bhf[4][2], blf[4][2];
#pragma unroll
            for (int nt = 0; nt < 4; nt++) {
                int nb = wn * 32 + nt * 8 + r8;
                bhf[nt][0] = __float_as_uint(Bh[(kk + lq) * GB_LD + nb]);
                bhf[nt][1] = __float_as_uint(Bh[(kk + 4 + lq) * GB_LD + nb]);
                if (PASSES >= 3) {
                    blf[nt][0] = __float_as_uint(Bl[(kk + lq) * GB_LD + nb]);
                    blf[nt][1] = __float_as_uint(Bl[(kk + 4 + lq) * GB_LD + nb]);
                }
            }
#pragma unroll
            for (int mt = 0; mt < 2; mt++)
#pragma unroll
                for (int nt = 0; nt < 4; nt++) {
                    mma8u(acc[mt][nt], ah[mt][0], ah[mt][1], ah[mt][2], ah[mt][3], bhf[nt][0], bhf[nt][1]);
                    if (PASSES >= 2)
                        mma8u(acc[mt][nt], al[mt][0], al[mt][1], al[mt][2], al[mt][3], bhf[nt][0], bhf[nt][1]);
                    if (PASSES >= 3)
                        mma8u(acc[mt][nt], ah[mt][0], ah[mt][1], ah[mt][2], ah[mt][3], blf[nt][0], blf[nt][1]);
                }
        }
        __syncthreads();
    }

    // ---- epilogue ----
#pragma unroll
    for (int mt = 0; mt < 2; mt++) {
        int r = row0 + wm * 32 + mt * 16 + r8;
#pragma unroll
        for (int nt = 0; nt < 4; nt++) {
            int c = wn * 32 + nt * 8 + lq * 2;
            if (MODE == 0) {
                int b = r >> 11, s = r & 2047;
                size_t base  = (((size_t)b * NHEAD + blockIdx.y) * SEQL + s) * DKH;
                size_t base2 = base + (size_t)8 * DKH;
                Cq[base + c]      = acc[mt][nt][0];
                Cq[base + c + 1]  = acc[mt][nt][1];
                Cq[base2 + c]     = acc[mt][nt][2];
                Cq[base2 + c + 1] = acc[mt][nt][3];
            } else {
                size_t base = (size_t)r * EMB + blockIdx.y * 64 + c;
                Cq[base]               = acc[mt][nt][0];
                Cq[base + 1]           = acc[mt][nt][1];
                Cq[base + 8 * EMB]     = acc[mt][nt][2];
                Cq[base + 8 * EMB + 1] = acc[mt][nt][3];
            }
        }
    }
}

// ---------------- flash attention (causal), 256 threads / 128-row Q blocks --
// K hi/lo: [64][FLD], V hi/lo: [64][VLD] (row-major [kv][d]), P/Q: [128][LDP].
#define FLD 68
#define VLD 72
#define LDP 68
#define F_KH 0
#define F_KL (64*FLD)
#define F_VH (2*64*FLD)
#define F_VL (2*64*FLD + 64*VLD)
#define F_PS (2*64*FLD + 2*64*VLD)
#define FSM_FLOATS (2*64*FLD + 2*64*VLD + 128*LDP)
#define FSM_BYTES  (FSM_FLOATS*4)
#define LOG2E 1.4426950408889634f

__global__ void __launch_bounds__(256) flash_kernel(const int* __restrict__ maskp)
{
    extern __shared__ float sm[];
    float* Kh = sm + F_KH;
    float* Kl = sm + F_KL;
    float* Vh = sm + F_VH;
    float* Vl = sm + F_VL;
    float* Ps = sm + F_PS;

    const int tid  = threadIdx.x;
    const int lane = tid & 31;
    const int warp = tid >> 5;                 // 0..7
    const int r8 = lane >> 2, lq = lane & 3;
    const int qt = blockIdx.x;                 // 128-row q block
    const int bh = blockIdx.y;
    const int b = bh >> 4, h = bh & 15;
    const int q0 = qt * 128;

    const float* Q = g_q + (size_t)bh * SEQL * DKH;
    const float* K = g_k + (size_t)bh * SEQL * DKH;
    const float* V = g_v + (size_t)bh * SEQL * DKH;

    // ---- stage Q tile (128 x 64) scaled by 8*log2(e) into Ps ----
    const float qscale = 8.f * LOG2E;
#pragma unroll
    for (int ii = 0; ii < 8; ii++) {
        int i = tid + ii * 256;
        int r = i >> 4, c4 = (i & 15) << 2;
        float4 v4 = *reinterpret_cast<const float4*>(Q + (size_t)(q0 + r) * DKH + c4);
        float* d = Ps + r * LDP + c4;
        d[0] = v4.x * qscale; d[1] = v4.y * qscale; d[2] = v4.z * qscale; d[3] = v4.w * qscale;
    }
    __syncthreads();

    const int rl = warp * 16 + r8;             // 0..127 (first of this thread's two q rows)
    unsigned qhi[8][4], qlo[8][4];
#pragma unroll
    for (int ks = 0; ks < 8; ks++) {
        split_tf32(Ps[rl * LDP + ks * 8 + lq],           qhi[ks][0], qlo[ks][0]);
        split_tf32(Ps[(rl + 8) * LDP + ks * 8 + lq],     qhi[ks][1], qlo[ks][1]);
        split_tf32(Ps[rl * LDP + ks * 8 + 4 + lq],       qhi[ks][2], qlo[ks][2]);
        split_tf32(Ps[(rl + 8) * LDP + ks * 8 + 4 + lq], qhi[ks][3], qlo[ks][3]);
    }

    float m[2] = { -1e30f, -1e30f };
    float l[2] = { 0.f, 0.f };
    float o[8][4];
#pragma unroll
    for (int i = 0; i < 8; i++)
#pragma unroll
        for (int j = 0; j < 4; j++) o[i][j] = 0.f;

    const int maskv = maskp[0];
    const int tdiag = 2 * qt + (warp >> 2);    // this warp's diagonal tile index
    const int ntiles = maskv ? (2 * qt + 2) : (SEQL / 64);

    for (int t = 0; t < ntiles; t++) {
        const int kv0 = t * 64;

        __syncthreads();   // previous iteration's PV done before K/V overwrite
        // ---- cooperative K / V load (64 x 64) with tf32 split ----
#pragma unroll
        for (int ii = 0; ii < 4; ii++) {
            int i = tid + ii * 256;
            int r = i >> 4, c4 = (i & 15) << 2;
            float4 k4 = *reinterpret_cast<const float4*>(K + (size_t)(kv0 + r) * DKH + c4);
            float kv[4] = { k4.x, k4.y, k4.z, k4.w };
#pragma unroll
            for (int j = 0; j < 4; j++) {
                unsigned hh, ll; split_tf32(kv[j], hh, ll);
                Kh[r * FLD + c4 + j] = __uint_as_float(hh);
                Kl[r * FLD + c4 + j] = __uint_as_float(ll);
            }
            float4 v4 = *reinterpret_cast<const float4*>(V + (size_t)(kv0 + r) * DKH + c4);
            float vv[4] = { v4.x, v4.y, v4.z, v4.w };
#pragma unroll
            for (int j = 0; j < 4; j++) {
                unsigned hh, ll; split_tf32(vv[j], hh, ll);
                Vh[r * VLD + c4 + j] = __uint_as_float(hh);
                Vl[r * VLD + c4 + j] = __uint_as_float(ll);
            }
        }
        __syncthreads();

        // fully-masked tile for this warp -> skip compute, keep barriers aligned
        if (maskv && t > tdiag) continue;

        // ---- S = Q K^T (TF32x3; scale folded into Q) ----
        float s[8][4];
#pragma unroll
        for (int i = 0; i < 8; i++)
#pragma unroll
            for (int j = 0; j < 4; j++) s[i][j] = 0.f;

#pragma unroll
        for (int ks = 0; ks < 8; ks++) {
            const int kk = ks * 8;
#pragma unroll
            for (int nt = 0; nt < 8; nt++) {
                int nb = nt * 8 + r8;
                unsigned bh0 = __float_as_uint(Kh[nb * FLD + kk + lq]);
                unsigned bh1 = __float_as_uint(Kh[nb * FLD + kk + 4 + lq]);
                unsigned bl0 = __float_as_uint(Kl[nb * FLD + kk + lq]);
                unsigned bl1 = __float_as_uint(Kl[nb * FLD + kk + 4 + lq]);
                mma8u(s[nt], qhi[ks][0], qhi[ks][1], qhi[ks][2], qhi[ks][3], bh0, bh1);
                mma8u(s[nt], qhi[ks][0], qhi[ks][1], qhi[ks][2], qhi[ks][3], bl0, bl1);
                mma8u(s[nt], qlo[ks][0], qlo[ks][1], qlo[ks][2], qlo[ks][3], bh0, bh1);
            }
        }

        // ---- causal mask on this warp's diagonal tile ----
        if (maskv && t == tdiag) {
            int rg0 = q0 + rl;
#pragma unroll
            for (int nt = 0; nt < 8; nt++) {
                int cg = kv0 + nt * 8 + lq * 2;
                if (cg > rg0)         s[nt][0] = -1e30f;
                if (cg + 1 > rg0)     s[nt][1] = -1e30f;
                if (cg > rg0 + 8)     s[nt][2] = -1e30f;
                if (cg + 1 > rg0 + 8) s[nt][3] = -1e30f;
            }
        }

        // ---- online softmax (base 2) ----
#pragma unroll
        for (int sub = 0; sub < 2; sub++) {
            float tm = -1e30f;
#pragma unroll
            for (int nt = 0; nt < 8; nt++)
                tm = fmaxf(tm, fmaxf(s[nt][2 * sub], s[nt][2 * sub + 1]));
            tm = fmaxf(tm, __shfl_xor_sync(0xffffffffu, tm, 1));
            tm = fmaxf(tm, __shfl_xor_sync(0xffffffffu, tm, 2));
            float mn = fmaxf(m[sub], tm);
            float alpha = exp2f(m[sub] - mn);
            float rs = 0.f;
#pragma unroll
            for (int nt = 0; nt < 8; nt++) {
                float p0 = exp2f(s[nt][2 * sub] - mn);
                float p1 = exp2f(s[nt][2 * sub + 1] - mn);
                s[nt][2 * sub] = p0; s[nt][2 * sub + 1] = p1;
                rs += p0 + p1;
            }
            rs += __shfl_xor_sync(0xffffffffu, rs, 1);
            rs += __shfl_xor_sync(0xffffffffu, rs, 2);
            l[sub] = l[sub] * alpha + rs;
            m[sub] = mn;
#pragma unroll
            for (int dt = 0; dt < 8; dt++) {
                o[dt][2 * sub]     *= alpha;
                o[dt][2 * sub + 1] *= alpha;
            }
        }

        // ---- store P (tf32-rounded) to warp-private rows (no sync needed) ----
#pragma unroll
        for (int nt = 0; nt < 8; nt++) {
            int c = nt * 8 + lq * 2;
            *reinterpret_cast<float2*>(Ps + rl * LDP + c) =
                make_float2(__uint_as_float(f2tf(s[nt][0])), __uint_as_float(f2tf(s[nt][1])));
            *reinterpret_cast<float2*>(Ps + (rl + 8) * LDP + c) =
                make_float2(__uint_as_float(f2tf(s[nt][2])), __uint_as_float(f2tf(s[nt][3])));
        }

        // ---- O += P * V (P single tf32, V hi+lo), skip masked k-slices ----
        int ksmax = (maskv && t == tdiag) ? (2 * (warp & 3) + 2) : 8;
#pragma unroll
        for (int ks = 0; ks < 8; ks++) {
            if (ks >= ksmax) break;
            int kkk = ks * 8 + lq;
            unsigned pa0 = __float_as_uint(Ps[rl * LDP + kkk]);
            unsigned pa1 = __float_as_uint(Ps[(rl + 8) * LDP + kkk]);
            unsigned pa2 = __float_as_uint(Ps[rl * LDP + kkk + 4]);
            unsigned pa3 = __float_as_uint(Ps[(rl + 8) * LDP + kkk + 4]);
#pragma unroll
            for (int dt = 0; dt < 8; dt++) {
                int db = dt * 8 + r8;
                unsigned bh0 = __float_as_uint(Vh[(ks * 8 + lq) * VLD + db]);
                unsigned bh1 = __float_as_uint(Vh[(ks * 8 + 4 + lq) * VLD + db]);
                unsigned bl0 = __float_as_uint(Vl[(ks * 8 + lq) * VLD + db]);
                unsigned bl1 = __float_as_uint(Vl[(ks * 8 + 4 + lq) * VLD + db]);
                mma8u(o[dt], pa0, pa1, pa2, pa3, bh0, bh1);
                mma8u(o[dt], pa0, pa1, pa2, pa3, bl0, bl1);
            }
        }
    }

    // ---- epilogue: attn[b, q, h, d] = O / l ----
    float i0 = 1.f / l[0];
    float i1 = 1.f / l[1];
    int rg = q0 + rl;
    size_t ob  = (((size_t)b * SEQL + rg) * NHEAD + h) * DKH;
    size_t ob2 = (((size_t)b * SEQL + rg + 8) * NHEAD + h) * DKH;
#pragma unroll
    for (int dt = 0; dt < 8; dt++) {
        int c = dt * 8 + lq * 2;
        g_attn[ob + c]      = o[dt][0] * i0;
        g_attn[ob + c + 1]  = o[dt][1] * i0;
        g_attn[ob2 + c]     = o[dt][2] * i1;
        g_attn[ob2 + c + 1] = o[dt][3] * i1;
    }
}

// ---------------- launcher ---------------------------------------------------
extern "C" void kernel_launch(void* const* d_in, const int* in_sizes, int n_in,
                              void* d_out, int out_size)
{
    const float* x_q = (const float*)d_in[0];
    const float* x_k = (const float*)d_in[1];
    const float* x_v = (const float*)d_in[2];
    const float* w_q = (const float*)d_in[3];
    const float* w_k = (const float*)d_in[4];
    const float* w_v = (const float*)d_in[5];
    const float* w_o = (const float*)d_in[6];
    const int*   msk = (const int*)d_in[7];
    float* out = (float*)d_out;

    cudaFuncSetAttribute((const void*)gemm_x3_kernel<0,3>, cudaFuncAttributeMaxDynamicSharedMemorySize, GSM_BYTES);
    cudaFuncSetAttribute((const void*)gemm_x3_kernel<0,2>, cudaFuncAttributeMaxDynamicSharedMemorySize, GSM_BYTES);
    cudaFuncSetAttribute((const void*)gemm_x3_kernel<1,2>, cudaFuncAttributeMaxDynamicSharedMemorySize, GSM_BYTES);
    cudaFuncSetAttribute((const void*)flash_kernel, cudaFuncAttributeMaxDynamicSharedMemorySize, FSM_BYTES);

    // Q, K projections: TF32x3 (score path needs precision)
    gemm_x3_kernel<0,3><<<dim3(MROWS / 128, NHEAD, 2), 256, GSM_BYTES>>>(
        x_q, x_k, x_v, w_q, w_k, w_v, nullptr, 0);
    // V projection: TF32x2
    gemm_x3_kernel<0,2><<<dim3(MROWS / 128, NHEAD, 1), 256, GSM_BYTES>>>(
        x_q, x_k, x_v, w_q, w_k, w_v, nullptr, 2);

    flash_kernel<<<dim3(SEQL / 128, BATCHN * NHEAD), 256, FSM_BYTES>>>(msk);

    // Output projection: TF32x2
    gemm_x3_kernel<1,2><<<dim3(MROWS / 128, EMB / 64, 1), 256, GSM_BYTES>>>(
        nullptr, nullptr, nullptr, w_o, nullptr, nullptr, out, 0);
}

// round 7
// speedup vs baseline: 2.2870x; 1.0249x over previous
#include <cuda_runtime.h>
#include <cuda_fp16.h>
#include <cstdint>

#define BATCHN 4
#define SEQL   2048
#define EMB    1024
#define NHEAD  16
#define DKH    64
#define MROWS  (BATCHN*SEQL)   /* 8192 */

// ---------------- scratch (static device globals; no runtime allocation) ----
__device__ float g_q[(size_t)BATCHN*NHEAD*SEQL*DKH];     // [b,h,s,d]
__device__ float g_k[(size_t)BATCHN*NHEAD*SEQL*DKH];
__device__ float g_v[(size_t)BATCHN*NHEAD*SEQL*DKH];
__device__ float g_attn[(size_t)MROWS*EMB];              // [b,s,h*d]

// ---------------- helpers ---------------------------------------------------
__device__ __forceinline__ unsigned f2tf(float x) {
    unsigned r;
    asm("cvt.rna.tf32.f32 %0, %1;" : "=r"(r) : "f"(x));
    return r;
}
__device__ __forceinline__ void split_tf32(float x, unsigned &hi, unsigned &lo) {
    hi = f2tf(x);
    lo = f2tf(x - __uint_as_float(hi));
}
// tf32 m16n8k8 (flash kernel)
__device__ __forceinline__ void mma8u(float c[4], unsigned a0, unsigned a1, unsigned a2, unsigned a3,
                                      unsigned b0, unsigned b1) {
    asm volatile(
        "mma.sync.aligned.m16n8k8.row.col.f32.tf32.tf32.f32 "
        "{%0,%1,%2,%3},{%4,%5,%6,%7},{%8,%9},{%0,%1,%2,%3};\n"
        : "+f"(c[0]), "+f"(c[1]), "+f"(c[2]), "+f"(c[3])
        : "r"(a0), "r"(a1), "r"(a2), "r"(a3), "r"(b0), "r"(b1));
}
// fp16 m16n8k16 (GEMM kernels)
__device__ __forceinline__ void mma16h(float c[4], unsigned a0, unsigned a1, unsigned a2, unsigned a3,
                                       unsigned b0, unsigned b1) {
    asm volatile(
        "mma.sync.aligned.m16n8k16.row.col.f32.f16.f16.f32 "
        "{%0,%1,%2,%3},{%4,%5,%6,%7},{%8,%9},{%0,%1,%2,%3};\n"
        : "+f"(c[0]), "+f"(c[1]), "+f"(c[2]), "+f"(c[3])
        : "r"(a0), "r"(a1), "r"(a2), "r"(a3), "r"(b0), "r"(b1));
}
// split (x0,x1) into fp16 hi pair + lo pair (packed half2 words, x0 in low)
__device__ __forceinline__ void split_h2(float x0, float x1, unsigned &hi, unsigned &lo) {
    __half2 H = __floats2half2_rn(x0, x1);
    float2 f = __half22float2(H);
    __half2 L = __floats2half2_rn(x0 - f.x, x1 - f.y);
    hi = *reinterpret_cast<unsigned*>(&H);
    lo = *reinterpret_cast<unsigned*>(&L);
}

// ---------------- GEMM (FP16 split, m16n8k16) --------------------------------
// A tiles: Ah2/Al2 [128 rows][20 half2-words] (16 data + 4 pad).
// B tiles: Bh2/Bl2 [16 kpairs][72 half2-words] (64 data + 8 pad).
// CTA 128 rows x 64 cols, 8 warps (warp tile 32x32: wm=warp>>1, wn=warp&1).
// MODE 0: per-head projections (sel = blockIdx.z + selbase -> q/k/v).
// MODE 1: output projection. A = g_attn, B = w_o, C = Cext.
#define AW 20
#define BW 72
#define G_AH 0
#define G_AL (128*AW)
#define G_BH (2*128*AW)
#define G_BL (2*128*AW + 16*BW)
#define GSM_WORDS (2*128*AW + 2*16*BW)
#define GSM_BYTES (GSM_WORDS*4)

template<int MODE, int PASSES>
__global__ void __launch_bounds__(256) gemm_h_kernel(
    const float* __restrict__ A0, const float* __restrict__ A1, const float* __restrict__ A2,
    const float* __restrict__ B0, const float* __restrict__ B1, const float* __restrict__ B2,
    float* __restrict__ Cext, int selbase)
{
    extern __shared__ unsigned smu[];
    unsigned* Ah2 = smu + G_AH;
    unsigned* Al2 = smu + G_AL;
    unsigned* Bh2 = smu + G_BH;
    unsigned* Bl2 = smu + G_BL;

    const int tid  = threadIdx.x;
    const int lane = tid & 31;
    const int warp = tid >> 5;
    const int wm = warp >> 1, wn = warp & 1;
    const int r8 = lane >> 2, lq = lane & 3;
    const int row0 = blockIdx.x * 128;

    const float* A;
    const float* Bt;
    int ldb, n0;
    float* Cq;
    if (MODE == 0) {
        int sel = blockIdx.z + selbase;
        A = sel == 0 ? A0 : (sel == 1 ? A1 : A2);
        const float* W = sel == 0 ? B0 : (sel == 1 ? B1 : B2);
        Bt = W + (size_t)blockIdx.y * EMB * 64; ldb = 64; n0 = 0;
        Cq = sel == 0 ? g_q : (sel == 1 ? g_k : g_v);
    } else {
        A = g_attn; Bt = B0; ldb = EMB; n0 = blockIdx.y * 64; Cq = Cext;
    }

    float acc[2][4][4];
#pragma unroll
    for (int i = 0; i < 2; i++)
#pragma unroll
        for (int j = 0; j < 4; j++)
#pragma unroll
            for (int r = 0; r < 4; r++) acc[i][j][r] = 0.f;

    // producer mappings
    const int am  = tid & 127;          // A row
    const int akh = (tid >> 7) * 16;    // A k-offset (16 elems)
    const int bn  = tid & 63;           // B col
    const int bk2 = (tid >> 6) * 4;     // B first kpair (4 kpairs per thread)

    float4 ra[4];
    float  rbv[8];

    // prologue: load chunk 0
#pragma unroll
    for (int i = 0; i < 4; i++)
        ra[i] = *reinterpret_cast<const float4*>(A + (size_t)(row0 + am) * EMB + akh + i * 4);
#pragma unroll
    for (int j = 0; j < 4; j++) {
        rbv[2*j]   = Bt[(size_t)(2 * (bk2 + j)) * ldb + n0 + bn];
        rbv[2*j+1] = Bt[(size_t)(2 * (bk2 + j) + 1) * ldb + n0 + bn];
    }

    for (int c = 0; c < EMB / 32; c++) {
        // ---- split + store current chunk ----
        {
            unsigned hw[8], lw[8];
#pragma unroll
            for (int i = 0; i < 4; i++) {
                split_h2(ra[i].x, ra[i].y, hw[2*i],   lw[2*i]);
                split_h2(ra[i].z, ra[i].w, hw[2*i+1], lw[2*i+1]);
            }
            int base = am * AW + (akh >> 1);
            *reinterpret_cast<uint4*>(Ah2 + base)     = make_uint4(hw[0], hw[1], hw[2], hw[3]);
            *reinterpret_cast<uint4*>(Ah2 + base + 4) = make_uint4(hw[4], hw[5], hw[6], hw[7]);
            *reinterpret_cast<uint4*>(Al2 + base)     = make_uint4(lw[0], lw[1], lw[2], lw[3]);
            *reinterpret_cast<uint4*>(Al2 + base + 4) = make_uint4(lw[4], lw[5], lw[6], lw[7]);
#pragma unroll
            for (int j = 0; j < 4; j++) {
                unsigned bh, bl;
                split_h2(rbv[2*j], rbv[2*j+1], bh, bl);
                Bh2[(bk2 + j) * BW + bn] = bh;
                Bl2[(bk2 + j) * BW + bn] = bl;
            }
        }
        __syncthreads();

        // ---- prefetch next chunk ----
        if (c + 1 < EMB / 32) {
            int k0 = (c + 1) * 32;
#pragma unroll
            for (int i = 0; i < 4; i++)
                ra[i] = *reinterpret_cast<const float4*>(A + (size_t)(row0 + am) * EMB + k0 + akh + i * 4);
#pragma unroll
            for (int j = 0; j < 4; j++) {
                rbv[2*j]   = Bt[(size_t)(k0 + 2 * (bk2 + j)) * ldb + n0 + bn];
                rbv[2*j+1] = Bt[(size_t)(k0 + 2 * (bk2 + j) + 1) * ldb + n0 + bn];
            }
        }

        // ---- compute: 2 x k16 steps ----
#pragma unroll
        for (int ks = 0; ks < 2; ks++) {
            const int kw = ks * 8;
            unsigned ah[2][4], al[2][4];
#pragma unroll
            for (int mt = 0; mt < 2; mt++) {
                int rw = (wm * 32 + mt * 16 + r8) * AW + kw + lq;
                ah[mt][0] = Ah2[rw];             al[mt][0] = Al2[rw];
                ah[mt][1] = Ah2[rw + 8 * AW];    al[mt][1] = Al2[rw + 8 * AW];
                ah[mt][2] = Ah2[rw + 4];         al[mt][2] = Al2[rw + 4];
                ah[mt][3] = Ah2[rw + 8 * AW + 4];al[mt][3] = Al2[rw + 8 * AW + 4];
            }
            unsigned bh[4][2], bl[4][2];
#pragma unroll
            for (int nt = 0; nt < 4; nt++) {
                int n = wn * 32 + nt * 8 + r8;
                bh[nt][0] = Bh2[(kw + lq) * BW + n];
                bh[nt][1] = Bh2[(kw + 4 + lq) * BW + n];
                if (PASSES >= 3) {
                    bl[nt][0] = Bl2[(kw + lq) * BW + n];
                    bl[nt][1] = Bl2[(kw + 4 + lq) * BW + n];
                }
            }
#pragma unroll
            for (int mt = 0; mt < 2; mt++)
#pragma unroll
                for (int nt = 0; nt < 4; nt++) {
                    mma16h(acc[mt][nt], ah[mt][0], ah[mt][1], ah[mt][2], ah[mt][3], bh[nt][0], bh[nt][1]);
                    if (PASSES >= 2)
                        mma16h(acc[mt][nt], al[mt][0], al[mt][1], al[mt][2], al[mt][3], bh[nt][0], bh[nt][1]);
                    if (PASSES >= 3)
                        mma16h(acc[mt][nt], ah[mt][0], ah[mt][1], ah[mt][2], ah[mt][3], bl[nt][0], bl[nt][1]);
                }
        }
        __syncthreads();
    }

    // ---- epilogue ----
#pragma unroll
    for (int mt = 0; mt < 2; mt++) {
        int r = row0 + wm * 32 + mt * 16 + r8;
#pragma unroll
        for (int nt = 0; nt < 4; nt++) {
            int cc = wn * 32 + nt * 8 + lq * 2;
            if (MODE == 0) {
                int b = r >> 11, s = r & 2047;
                size_t base  = (((size_t)b * NHEAD + blockIdx.y) * SEQL + s) * DKH;
                size_t base2 = base + (size_t)8 * DKH;
                Cq[base + cc]      = acc[mt][nt][0];
                Cq[base + cc + 1]  = acc[mt][nt][1];
                Cq[base2 + cc]     = acc[mt][nt][2];
                Cq[base2 + cc + 1] = acc[mt][nt][3];
            } else {
                size_t base = (size_t)r * EMB + blockIdx.y * 64 + cc;
                Cq[base]               = acc[mt][nt][0];
                Cq[base + 1]           = acc[mt][nt][1];
                Cq[base + 8 * EMB]     = acc[mt][nt][2];
                Cq[base + 8 * EMB + 1] = acc[mt][nt][3];
            }
        }
    }
}

// ---------------- flash attention (causal) — unchanged from R6 ---------------
#define FLD 68
#define VLD 72
#define LDP 68
#define F_KH 0
#define F_KL (64*FLD)
#define F_VH (2*64*FLD)
#define F_VL (2*64*FLD + 64*VLD)
#define F_PS (2*64*FLD + 2*64*VLD)
#define FSM_FLOATS (2*64*FLD + 2*64*VLD + 128*LDP)
#define FSM_BYTES  (FSM_FLOATS*4)
#define LOG2E 1.4426950408889634f

__global__ void __launch_bounds__(256) flash_kernel(const int* __restrict__ maskp)
{
    extern __shared__ float sm[];
    float* Kh = sm + F_KH;
    float* Kl = sm + F_KL;
    float* Vh = sm + F_VH;
    float* Vl = sm + F_VL;
    float* Ps = sm + F_PS;

    const int tid  = threadIdx.x;
    const int lane = tid & 31;
    const int warp = tid >> 5;
    const int r8 = lane >> 2, lq = lane & 3;
    const int qt = blockIdx.x;
    const int bh = blockIdx.y;
    const int b = bh >> 4, h = bh & 15;
    const int q0 = qt * 128;

    const float* Q = g_q + (size_t)bh * SEQL * DKH;
    const float* K = g_k + (size_t)bh * SEQL * DKH;
    const float* V = g_v + (size_t)bh * SEQL * DKH;

    const float qscale = 8.f * LOG2E;
#pragma unroll
    for (int ii = 0; ii < 8; ii++) {
        int i = tid + ii * 256;
        int r = i >> 4, c4 = (i & 15) << 2;
        float4 v4 = *reinterpret_cast<const float4*>(Q + (size_t)(q0 + r) * DKH + c4);
        float* d = Ps + r * LDP + c4;
        d[0] = v4.x * qscale; d[1] = v4.y * qscale; d[2] = v4.z * qscale; d[3] = v4.w * qscale;
    }
    __syncthreads();

    const int rl = warp * 16 + r8;
    unsigned qhi[8][4], qlo[8][4];
#pragma unroll
    for (int ks = 0; ks < 8; ks++) {
        split_tf32(Ps[rl * LDP + ks * 8 + lq],           qhi[ks][0], qlo[ks][0]);
        split_tf32(Ps[(rl + 8) * LDP + ks * 8 + lq],     qhi[ks][1], qlo[ks][1]);
        split_tf32(Ps[rl * LDP + ks * 8 + 4 + lq],       qhi[ks][2], qlo[ks][2]);
        split_tf32(Ps[(rl + 8) * LDP + ks * 8 + 4 + lq], qhi[ks][3], qlo[ks][3]);
    }

    float m[2] = { -1e30f, -1e30f };
    float l[2] = { 0.f, 0.f };
    float o[8][4];
#pragma unroll
    for (int i = 0; i < 8; i++)
#pragma unroll
        for (int j = 0; j < 4; j++) o[i][j] = 0.f;

    const int maskv = maskp[0];
    const int tdiag = 2 * qt + (warp >> 2);
    const int ntiles = maskv ? (2 * qt + 2) : (SEQL / 64);

    for (int t = 0; t < ntiles; t++) {
        const int kv0 = t * 64;

        __syncthreads();
#pragma unroll
        for (int ii = 0; ii < 4; ii++) {
            int i = tid + ii * 256;
            int r = i >> 4, c4 = (i & 15) << 2;
            float4 k4 = *reinterpret_cast<const float4*>(K + (size_t)(kv0 + r) * DKH + c4);
            float kv[4] = { k4.x, k4.y, k4.z, k4.w };
#pragma unroll
            for (int j = 0; j < 4; j++) {
                unsigned hh, ll; split_tf32(kv[j], hh, ll);
                Kh[r * FLD + c4 + j] = __uint_as_float(hh);
                Kl[r * FLD + c4 + j] = __uint_as_float(ll);
            }
            float4 v4 = *reinterpret_cast<const float4*>(V + (size_t)(kv0 + r) * DKH + c4);
            float vv[4] = { v4.x, v4.y, v4.z, v4.w };
#pragma unroll
            for (int j = 0; j < 4; j++) {
                unsigned hh, ll; split_tf32(vv[j], hh, ll);
                Vh[r * VLD + c4 + j] = __uint_as_float(hh);
                Vl[r * VLD + c4 + j] = __uint_as_float(ll);
            }
        }
        __syncthreads();

        if (maskv && t > tdiag) continue;

        float s[8][4];
#pragma unroll
        for (int i = 0; i < 8; i++)
#pragma unroll
            for (int j = 0; j < 4; j++) s[i][j] = 0.f;

#pragma unroll
        for (int ks = 0; ks < 8; ks++) {
            const int kk = ks * 8;
#pragma unroll
            for (int nt = 0; nt < 8; nt++) {
                int nb = nt * 8 + r8;
                unsigned bh0 = __float_as_uint(Kh[nb * FLD + kk + lq]);
                unsigned bh1 = __float_as_uint(Kh[nb * FLD + kk + 4 + lq]);
                unsigned bl0 = __float_as_uint(Kl[nb * FLD + kk + lq]);
                unsigned bl1 = __float_as_uint(Kl[nb * FLD + kk + 4 + lq]);
                mma8u(s[nt], qhi[ks][0], qhi[ks][1], qhi[ks][2], qhi[ks][3], bh0, bh1);
                mma8u(s[nt], qhi[ks][0], qhi[ks][1], qhi[ks][2], qhi[ks][3], bl0, bl1);
                mma8u(s[nt], qlo[ks][0], qlo[ks][1], qlo[ks][2], qlo[ks][3], bh0, bh1);
            }
        }

        if (maskv && t == tdiag) {
            int rg0 = q0 + rl;
#pragma unroll
            for (int nt = 0; nt < 8; nt++) {
                int cg = kv0 + nt * 8 + lq * 2;
                if (cg > rg0)         s[nt][0] = -1e30f;
                if (cg + 1 > rg0)     s[nt][1] = -1e30f;
                if (cg > rg0 + 8)     s[nt][2] = -1e30f;
                if (cg + 1 > rg0 + 8) s[nt][3] = -1e30f;
            }
        }

#pragma unroll
        for (int sub = 0; sub < 2; sub++) {
            float tm = -1e30f;
#pragma unroll
            for (int nt = 0; nt < 8; nt++)
                tm = fmaxf(tm, fmaxf(s[nt][2 * sub], s[nt][2 * sub + 1]));
            tm = fmaxf(tm, __shfl_xor_sync(0xffffffffu, tm, 1));
            tm = fmaxf(tm, __shfl_xor_sync(0xffffffffu, tm, 2));
            float mn = fmaxf(m[sub], tm);
            float alpha = exp2f(m[sub] - mn);
            float rs = 0.f;
#pragma unroll
            for (int nt = 0; nt < 8; nt++) {
                float p0 = exp2f(s[nt][2 * sub] - mn);
                float p1 = exp2f(s[nt][2 * sub + 1] - mn);
                s[nt][2 * sub] = p0; s[nt][2 * sub + 1] = p1;
                rs += p0 + p1;
            }
            rs += __shfl_xor_sync(0xffffffffu, rs, 1);
            rs += __shfl_xor_sync(0xffffffffu, rs, 2);
            l[sub] = l[sub] * alpha + rs;
            m[sub] = mn;
#pragma unroll
            for (int dt = 0; dt < 8; dt++) {
                o[dt][2 * sub]     *= alpha;
                o[dt][2 * sub + 1] *= alpha;
            }
        }

#pragma unroll
        for (int nt = 0; nt < 8; nt++) {
            int c = nt * 8 + lq * 2;
            *reinterpret_cast<float2*>(Ps + rl * LDP + c) =
                make_float2(__uint_as_float(f2tf(s[nt][0])), __uint_as_float(f2tf(s[nt][1])));
            *reinterpret_cast<float2*>(Ps + (rl + 8) * LDP + c) =
                make_float2(__uint_as_float(f2tf(s[nt][2])), __uint_as_float(f2tf(s[nt][3])));
        }

        int ksmax = (maskv && t == tdiag) ? (2 * (warp & 3) + 2) : 8;
#pragma unroll
        for (int ks = 0; ks < 8; ks++) {
            if (ks >= ksmax) break;
            int kkk = ks * 8 + lq;
            unsigned pa0 = __float_as_uint(Ps[rl * LDP + kkk]);
            unsigned pa1 = __float_as_uint(Ps[(rl + 8) * LDP + kkk]);
            unsigned pa2 = __float_as_uint(Ps[rl * LDP + kkk + 4]);
            unsigned pa3 = __float_as_uint(Ps[(rl + 8) * LDP + kkk + 4]);
#pragma unroll
            for (int dt = 0; dt < 8; dt++) {
                int db = dt * 8 + r8;
                unsigned bh0 = __float_as_uint(Vh[(ks * 8 + lq) * VLD + db]);
                unsigned bh1 = __float_as_uint(Vh[(ks * 8 + 4 + lq) * VLD + db]);
                unsigned bl0 = __float_as_uint(Vl[(ks * 8 + lq) * VLD + db]);
                unsigned bl1 = __float_as_uint(Vl[(ks * 8 + 4 + lq) * VLD + db]);
                mma8u(o[dt], pa0, pa1, pa2, pa3, bh0, bh1);
                mma8u(o[dt], pa0, pa1, pa2, pa3, bl0, bl1);
            }
        }
    }

    float i0 = 1.f / l[0];
    float i1 = 1.f / l[1];
    int rg = q0 + rl;
    size_t ob  = (((size_t)b * SEQL + rg) * NHEAD + h) * DKH;
    size_t ob2 = (((size_t)b * SEQL + rg + 8) * NHEAD + h) * DKH;
#pragma unroll
    for (int dt = 0; dt < 8; dt++) {
        int c = dt * 8 + lq * 2;
        g_attn[ob + c]      = o[dt][0] * i0;
        g_attn[ob + c + 1]  = o[dt][1] * i0;
        g_attn[ob2 + c]     = o[dt][2] * i1;
        g_attn[ob2 + c + 1] = o[dt][3] * i1;
    }
}

// ---------------- launcher ---------------------------------------------------
extern "C" void kernel_launch(void* const* d_in, const int* in_sizes, int n_in,
                              void* d_out, int out_size)
{
    const float* x_q = (const float*)d_in[0];
    const float* x_k = (const float*)d_in[1];
    const float* x_v = (const float*)d_in[2];
    const float* w_q = (const float*)d_in[3];
    const float* w_k = (const float*)d_in[4];
    const float* w_v = (const float*)d_in[5];
    const float* w_o = (const float*)d_in[6];
    const int*   msk = (const int*)d_in[7];
    float* out = (float*)d_out;

    cudaFuncSetAttribute((const void*)gemm_h_kernel<0,3>, cudaFuncAttributeMaxDynamicSharedMemorySize, GSM_BYTES);
    cudaFuncSetAttribute((const void*)gemm_h_kernel<0,2>, cudaFuncAttributeMaxDynamicSharedMemorySize, GSM_BYTES);
    cudaFuncSetAttribute((const void*)gemm_h_kernel<1,2>, cudaFuncAttributeMaxDynamicSharedMemorySize, GSM_BYTES);
    cudaFuncSetAttribute((const void*)flash_kernel, cudaFuncAttributeMaxDynamicSharedMemorySize, FSM_BYTES);

    // Q, K projections: fp16 x3 (score path needs precision)
    gemm_h_kernel<0,3><<<dim3(MROWS / 128, NHEAD, 2), 256, GSM_BYTES>>>(
        x_q, x_k, x_v, w_q, w_k, w_v, nullptr, 0);
    // V projection: fp16 x2
    gemm_h_kernel<0,2><<<dim3(MROWS / 128, NHEAD, 1), 256, GSM_BYTES>>>(
        x_q, x_k, x_v, w_q, w_k, w_v, nullptr, 2);

    flash_kernel<<<dim3(SEQL / 128, BATCHN * NHEAD), 256, FSM_BYTES>>>(msk);

    // Output projection: fp16 x2
    gemm_h_kernel<1,2><<<dim3(MROWS / 128, EMB / 64, 1), 256, GSM_BYTES>>>(
        nullptr, nullptr, nullptr, w_o, nullptr, nullptr, out, 0);
}

// round 8
// speedup vs baseline: 2.5922x; 1.1334x over previous
#include <cuda_runtime.h>
#include <cuda_fp16.h>
#include <cstdint>

#define BATCHN 4
#define SEQL   2048
#define EMB    1024
#define NHEAD  16
#define DKH    64
#define MROWS  (BATCHN*SEQL)   /* 8192 */

// ---------------- scratch (static device globals; no runtime allocation) ----
__device__ float g_q[(size_t)BATCHN*NHEAD*SEQL*DKH];     // [b,h,s,d]
__device__ float g_k[(size_t)BATCHN*NHEAD*SEQL*DKH];
__device__ float g_v[(size_t)BATCHN*NHEAD*SEQL*DKH];
__device__ float g_attn[(size_t)MROWS*EMB];              // [b,s,h*d]

// ---------------- helpers ---------------------------------------------------
__device__ __forceinline__ void mma16h(float c[4], unsigned a0, unsigned a1, unsigned a2, unsigned a3,
                                       unsigned b0, unsigned b1) {
    asm volatile(
        "mma.sync.aligned.m16n8k16.row.col.f32.f16.f16.f32 "
        "{%0,%1,%2,%3},{%4,%5,%6,%7},{%8,%9},{%0,%1,%2,%3};\n"
        : "+f"(c[0]), "+f"(c[1]), "+f"(c[2]), "+f"(c[3])
        : "r"(a0), "r"(a1), "r"(a2), "r"(a3), "r"(b0), "r"(b1));
}
// split (x0,x1) into fp16 hi pair + lo pair (packed half2 words, x0 in low)
__device__ __forceinline__ void split_h2(float x0, float x1, unsigned &hi, unsigned &lo) {
    __half2 H = __floats2half2_rn(x0, x1);
    float2 f = __half22float2(H);
    __half2 L = __floats2half2_rn(x0 - f.x, x1 - f.y);
    hi = *reinterpret_cast<unsigned*>(&H);
    lo = *reinterpret_cast<unsigned*>(&L);
}
__device__ __forceinline__ unsigned pack_h2(float x0, float x1) {
    __half2 H = __floats2half2_rn(x0, x1);
    return *reinterpret_cast<unsigned*>(&H);
}

// ---------------- GEMM (FP16 split, m16n8k16, double-buffered) ---------------
#define AW 20
#define BW 72
#define G_AH 0
#define G_AL (128*AW)
#define G_BH (2*128*AW)
#define G_BL (2*128*AW + 16*BW)
#define GSTAGE (2*128*AW + 2*16*BW)      /* 7424 words */
#define GSM_BYTES (2*GSTAGE*4)

template<int MODE, int PASSES>
__global__ void __launch_bounds__(256) gemm_h_kernel(
    const float* __restrict__ A0, const float* __restrict__ A1, const float* __restrict__ A2,
    const float* __restrict__ B0, const float* __restrict__ B1, const float* __restrict__ B2,
    float* __restrict__ Cext, int selbase)
{
    extern __shared__ unsigned smu[];

    const int tid  = threadIdx.x;
    const int lane = tid & 31;
    const int warp = tid >> 5;
    const int wm = warp >> 1, wn = warp & 1;
    const int r8 = lane >> 2, lq = lane & 3;
    const int row0 = blockIdx.x * 128;

    const float* A;
    const float* Bt;
    int ldb, n0;
    float* Cq;
    if (MODE == 0) {
        int sel = blockIdx.z + selbase;
        A = sel == 0 ? A0 : (sel == 1 ? A1 : A2);
        const float* W = sel == 0 ? B0 : (sel == 1 ? B1 : B2);
        Bt = W + (size_t)blockIdx.y * EMB * 64; ldb = 64; n0 = 0;
        Cq = sel == 0 ? g_q : (sel == 1 ? g_k : g_v);
    } else {
        A = g_attn; Bt = B0; ldb = EMB; n0 = blockIdx.y * 64; Cq = Cext;
    }

    float acc[2][4][4];
#pragma unroll
    for (int i = 0; i < 2; i++)
#pragma unroll
        for (int j = 0; j < 4; j++)
#pragma unroll
            for (int r = 0; r < 4; r++) acc[i][j][r] = 0.f;

    const int am  = tid & 127;
    const int akh = (tid >> 7) * 16;
    const int bn  = tid & 63;
    const int bk2 = (tid >> 6) * 4;

    float4 ra[4];
    float  rbv[8];

    // prologue: load + store chunk 0 into stage 0
#pragma unroll
    for (int i = 0; i < 4; i++)
        ra[i] = *reinterpret_cast<const float4*>(A + (size_t)(row0 + am) * EMB + akh + i * 4);
#pragma unroll
    for (int j = 0; j < 4; j++) {
        rbv[2*j]   = Bt[(size_t)(2 * (bk2 + j)) * ldb + n0 + bn];
        rbv[2*j+1] = Bt[(size_t)(2 * (bk2 + j) + 1) * ldb + n0 + bn];
    }
    {
        unsigned hw[8], lw[8];
#pragma unroll
        for (int i = 0; i < 4; i++) {
            split_h2(ra[i].x, ra[i].y, hw[2*i],   lw[2*i]);
            split_h2(ra[i].z, ra[i].w, hw[2*i+1], lw[2*i+1]);
        }
        int base = am * AW + (akh >> 1);
        *reinterpret_cast<uint4*>(smu + G_AH + base)     = make_uint4(hw[0], hw[1], hw[2], hw[3]);
        *reinterpret_cast<uint4*>(smu + G_AH + base + 4) = make_uint4(hw[4], hw[5], hw[6], hw[7]);
        *reinterpret_cast<uint4*>(smu + G_AL + base)     = make_uint4(lw[0], lw[1], lw[2], lw[3]);
        *reinterpret_cast<uint4*>(smu + G_AL + base + 4) = make_uint4(lw[4], lw[5], lw[6], lw[7]);
#pragma unroll
        for (int j = 0; j < 4; j++) {
            unsigned bh, bl;
            split_h2(rbv[2*j], rbv[2*j+1], bh, bl);
            smu[G_BH + (bk2 + j) * BW + bn] = bh;
            smu[G_BL + (bk2 + j) * BW + bn] = bl;
        }
    }
    __syncthreads();

    for (int c = 0; c < EMB / 32; c++) {
        const int st = c & 1;
        unsigned* Ah2 = smu + st * GSTAGE + G_AH;
        unsigned* Al2 = smu + st * GSTAGE + G_AL;
        unsigned* Bh2 = smu + st * GSTAGE + G_BH;
        unsigned* Bl2 = smu + st * GSTAGE + G_BL;

        const bool more = (c + 1 < EMB / 32);
        if (more) {
            int k0 = (c + 1) * 32;
#pragma unroll
            for (int i = 0; i < 4; i++)
                ra[i] = *reinterpret_cast<const float4*>(A + (size_t)(row0 + am) * EMB + k0 + akh + i * 4);
#pragma unroll
            for (int j = 0; j < 4; j++) {
                rbv[2*j]   = Bt[(size_t)(k0 + 2 * (bk2 + j)) * ldb + n0 + bn];
                rbv[2*j+1] = Bt[(size_t)(k0 + 2 * (bk2 + j) + 1) * ldb + n0 + bn];
            }
        }

        // ---- compute from stage st ----
#pragma unroll
        for (int ks = 0; ks < 2; ks++) {
            const int kw = ks * 8;
            unsigned ah[2][4], al[2][4];
#pragma unroll
            for (int mt = 0; mt < 2; mt++) {
                int rw = (wm * 32 + mt * 16 + r8) * AW + kw + lq;
                ah[mt][0] = Ah2[rw];              al[mt][0] = Al2[rw];
                ah[mt][1] = Ah2[rw + 8 * AW];     al[mt][1] = Al2[rw + 8 * AW];
                ah[mt][2] = Ah2[rw + 4];          al[mt][2] = Al2[rw + 4];
                ah[mt][3] = Ah2[rw + 8 * AW + 4]; al[mt][3] = Al2[rw + 8 * AW + 4];
            }
            unsigned bh[4][2], bl[4][2];
#pragma unroll
            for (int nt = 0; nt < 4; nt++) {
                int n = wn * 32 + nt * 8 + r8;
                bh[nt][0] = Bh2[(kw + lq) * BW + n];
                bh[nt][1] = Bh2[(kw + 4 + lq) * BW + n];
                if (PASSES >= 3) {
                    bl[nt][0] = Bl2[(kw + lq) * BW + n];
                    bl[nt][1] = Bl2[(kw + 4 + lq) * BW + n];
                }
            }
#pragma unroll
            for (int mt = 0; mt < 2; mt++)
#pragma unroll
                for (int nt = 0; nt < 4; nt++) {
                    mma16h(acc[mt][nt], ah[mt][0], ah[mt][1], ah[mt][2], ah[mt][3], bh[nt][0], bh[nt][1]);
                    if (PASSES >= 2)
                        mma16h(acc[mt][nt], al[mt][0], al[mt][1], al[mt][2], al[mt][3], bh[nt][0], bh[nt][1]);
                    if (PASSES >= 3)
                        mma16h(acc[mt][nt], ah[mt][0], ah[mt][1], ah[mt][2], ah[mt][3], bl[nt][0], bl[nt][1]);
                }
        }

        // ---- store chunk c+1 into stage st^1 ----
        if (more) {
            unsigned* Ah2n = smu + (st ^ 1) * GSTAGE + G_AH;
            unsigned* Al2n = smu + (st ^ 1) * GSTAGE + G_AL;
            unsigned* Bh2n = smu + (st ^ 1) * GSTAGE + G_BH;
            unsigned* Bl2n = smu + (st ^ 1) * GSTAGE + G_BL;
            unsigned hw[8], lw[8];
#pragma unroll
            for (int i = 0; i < 4; i++) {
                split_h2(ra[i].x, ra[i].y, hw[2*i],   lw[2*i]);
                split_h2(ra[i].z, ra[i].w, hw[2*i+1], lw[2*i+1]);
            }
            int base = am * AW + (akh >> 1);
            *reinterpret_cast<uint4*>(Ah2n + base)     = make_uint4(hw[0], hw[1], hw[2], hw[3]);
            *reinterpret_cast<uint4*>(Ah2n + base + 4) = make_uint4(hw[4], hw[5], hw[6], hw[7]);
            *reinterpret_cast<uint4*>(Al2n + base)     = make_uint4(lw[0], lw[1], lw[2], lw[3]);
            *reinterpret_cast<uint4*>(Al2n + base + 4) = make_uint4(lw[4], lw[5], lw[6], lw[7]);
#pragma unroll
            for (int j = 0; j < 4; j++) {
                unsigned bh, bl;
                split_h2(rbv[2*j], rbv[2*j+1], bh, bl);
                Bh2n[(bk2 + j) * BW + bn] = bh;
                Bl2n[(bk2 + j) * BW + bn] = bl;
            }
        }
        __syncthreads();
    }

    // ---- epilogue ----
#pragma unroll
    for (int mt = 0; mt < 2; mt++) {
        int r = row0 + wm * 32 + mt * 16 + r8;
#pragma unroll
        for (int nt = 0; nt < 4; nt++) {
            int cc = wn * 32 + nt * 8 + lq * 2;
            if (MODE == 0) {
                int b = r >> 11, s = r & 2047;
                size_t base  = (((size_t)b * NHEAD + blockIdx.y) * SEQL + s) * DKH;
                size_t base2 = base + (size_t)8 * DKH;
                Cq[base + cc]      = acc[mt][nt][0];
                Cq[base + cc + 1]  = acc[mt][nt][1];
                Cq[base2 + cc]     = acc[mt][nt][2];
                Cq[base2 + cc + 1] = acc[mt][nt][3];
            } else {
                size_t base = (size_t)r * EMB + blockIdx.y * 64 + cc;
                Cq[base]               = acc[mt][nt][0];
                Cq[base + 1]           = acc[mt][nt][1];
                Cq[base + 8 * EMB]     = acc[mt][nt][2];
                Cq[base + 8 * EMB + 1] = acc[mt][nt][3];
            }
        }
    }
}

// ---------------- flash attention (causal), full fp16 split ------------------
// Q: Qh2/Ql2 [128 rows][QW=36 d-pair words]   (region reused by K/V after extract)
// K: Kh2/Kl2 [64 kv][KW=36 d-pair words]
// V: Vh2/Vl2 [32 kv-pairs][PW=68 d words]     (V^T pairs along kv)
#define QW 36
#define KW 36
#define PW 68
#define FQ_H 0
#define FQ_L (128*QW)
#define FK_H 0
#define FK_L (64*KW)
#define FV_H (2*64*KW)
#define FV_L (2*64*KW + 32*PW)
#define FSM_WORDS (2*128*QW)
#define FSM_BYTES (FSM_WORDS*4)
#define LOG2E 1.4426950408889634f

__global__ void __launch_bounds__(256) flash_kernel(const int* __restrict__ maskp)
{
    extern __shared__ unsigned smw[];

    const int tid  = threadIdx.x;
    const int lane = tid & 31;
    const int warp = tid >> 5;                 // 0..7
    const int r8 = lane >> 2, lq = lane & 3;
    const int qt = blockIdx.x;                 // 128-row q block
    const int bh = blockIdx.y;
    const int b = bh >> 4, h = bh & 15;
    const int q0 = qt * 128;

    const float* Q = g_q + (size_t)bh * SEQL * DKH;
    const float* K = g_k + (size_t)bh * SEQL * DKH;
    const float* V = g_v + (size_t)bh * SEQL * DKH;

    // ---- stage Q tile (128 x 64), scaled, split into Qh2/Ql2 ----
    const float qscale = 8.f * LOG2E;
#pragma unroll
    for (int ii = 0; ii < 8; ii++) {
        int i = tid + ii * 256;
        int r = i >> 4, c4 = (i & 15) << 2;
        float4 v4 = *reinterpret_cast<const float4*>(Q + (size_t)(q0 + r) * DKH + c4);
        unsigned h01, l01, h23, l23;
        split_h2(v4.x * qscale, v4.y * qscale, h01, l01);
        split_h2(v4.z * qscale, v4.w * qscale, h23, l23);
        int base = r * QW + (c4 >> 1);
        *reinterpret_cast<uint2*>(smw + FQ_H + base) = make_uint2(h01, h23);
        *reinterpret_cast<uint2*>(smw + FQ_L + base) = make_uint2(l01, l23);
    }
    __syncthreads();

    const int rl = warp * 16 + r8;             // first of this thread's two q rows
    unsigned qh[4][4], ql[4][4];
#pragma unroll
    for (int ks = 0; ks < 4; ks++) {
        int base = rl * QW + ks * 8 + lq;
        qh[ks][0] = smw[FQ_H + base];
        qh[ks][1] = smw[FQ_H + base + 8 * QW];
        qh[ks][2] = smw[FQ_H + base + 4];
        qh[ks][3] = smw[FQ_H + base + 8 * QW + 4];
        ql[ks][0] = smw[FQ_L + base];
        ql[ks][1] = smw[FQ_L + base + 8 * QW];
        ql[ks][2] = smw[FQ_L + base + 4];
        ql[ks][3] = smw[FQ_L + base + 8 * QW + 4];
    }
    __syncthreads();   // all Q extracted before K/V overwrite the region

    float m[2] = { -1e30f, -1e30f };
    float l[2] = { 0.f, 0.f };
    float o[8][4];
#pragma unroll
    for (int i = 0; i < 8; i++)
#pragma unroll
        for (int j = 0; j < 4; j++) o[i][j] = 0.f;

    const int maskv = maskp[0];
    const int tdiag = 2 * qt + (warp >> 2);
    const int ntiles = maskv ? (2 * qt + 2) : (SEQL / 64);

    __half* vhp = reinterpret_cast<__half*>(smw + FV_H);
    __half* vlp = reinterpret_cast<__half*>(smw + FV_L);

    for (int t = 0; t < ntiles; t++) {
        const int kv0 = t * 64;

        if (t > 0) __syncthreads();   // prev PV reads done before overwrite
        // ---- cooperative K / V load (64 x 64) with fp16 split ----
#pragma unroll
        for (int ii = 0; ii < 4; ii++) {
            int i = tid + ii * 256;
            int r = i >> 4, c4 = (i & 15) << 2;
            float4 k4 = *reinterpret_cast<const float4*>(K + (size_t)(kv0 + r) * DKH + c4);
            unsigned h01, l01, h23, l23;
            split_h2(k4.x, k4.y, h01, l01);
            split_h2(k4.z, k4.w, h23, l23);
            int kb = r * KW + (c4 >> 1);
            *reinterpret_cast<uint2*>(smw + FK_H + kb) = make_uint2(h01, h23);
            *reinterpret_cast<uint2*>(smw + FK_L + kb) = make_uint2(l01, l23);

            float4 v4 = *reinterpret_cast<const float4*>(V + (size_t)(kv0 + r) * DKH + c4);
            float vv[4] = { v4.x, v4.y, v4.z, v4.w };
            int p = r >> 1, rb = r & 1;
#pragma unroll
            for (int j = 0; j < 4; j++) {
                __half hv = __float2half_rn(vv[j]);
                __half lv = __float2half_rn(vv[j] - __half2float(hv));
                int hidx = (p * PW + c4 + j) * 2 + rb;
                vhp[hidx] = hv;
                vlp[hidx] = lv;
            }
        }
        __syncthreads();

        if (maskv && t > tdiag) continue;

        // ---- S = Q K^T (fp16 x3; scale folded into Q) ----
        float s[8][4];
#pragma unroll
        for (int i = 0; i < 8; i++)
#pragma unroll
            for (int j = 0; j < 4; j++) s[i][j] = 0.f;

#pragma unroll
        for (int ks = 0; ks < 4; ks++) {
#pragma unroll
            for (int nt = 0; nt < 8; nt++) {
                int n = nt * 8 + r8;
                unsigned bh0 = smw[FK_H + n * KW + ks * 8 + lq];
                unsigned bh1 = smw[FK_H + n * KW + ks * 8 + lq + 4];
                unsigned bl0 = smw[FK_L + n * KW + ks * 8 + lq];
                unsigned bl1 = smw[FK_L + n * KW + ks * 8 + lq + 4];
                mma16h(s[nt], qh[ks][0], qh[ks][1], qh[ks][2], qh[ks][3], bh0, bh1);
                mma16h(s[nt], qh[ks][0], qh[ks][1], qh[ks][2], qh[ks][3], bl0, bl1);
                mma16h(s[nt], ql[ks][0], ql[ks][1], ql[ks][2], ql[ks][3], bh0, bh1);
            }
        }

        // ---- causal mask on this warp's diagonal tile ----
        if (maskv && t == tdiag) {
            int rg0 = q0 + rl;
#pragma unroll
            for (int nt = 0; nt < 8; nt++) {
                int cg = kv0 + nt * 8 + lq * 2;
                if (cg > rg0)         s[nt][0] = -1e30f;
                if (cg + 1 > rg0)     s[nt][1] = -1e30f;
                if (cg > rg0 + 8)     s[nt][2] = -1e30f;
                if (cg + 1 > rg0 + 8) s[nt][3] = -1e30f;
            }
        }

        // ---- online softmax (base 2) ----
#pragma unroll
        for (int sub = 0; sub < 2; sub++) {
            float tm = -1e30f;
#pragma unroll
            for (int nt = 0; nt < 8; nt++)
                tm = fmaxf(tm, fmaxf(s[nt][2 * sub], s[nt][2 * sub + 1]));
            tm = fmaxf(tm, __shfl_xor_sync(0xffffffffu, tm, 1));
            tm = fmaxf(tm, __shfl_xor_sync(0xffffffffu, tm, 2));
            float mn = fmaxf(m[sub], tm);
            float alpha = exp2f(m[sub] - mn);
            float rs = 0.f;
#pragma unroll
            for (int nt = 0; nt < 8; nt++) {
                float p0 = exp2f(s[nt][2 * sub] - mn);
                float p1 = exp2f(s[nt][2 * sub + 1] - mn);
                s[nt][2 * sub] = p0; s[nt][2 * sub + 1] = p1;
                rs += p0 + p1;
            }
            rs += __shfl_xor_sync(0xffffffffu, rs, 1);
            rs += __shfl_xor_sync(0xffffffffu, rs, 2);
            l[sub] = l[sub] * alpha + rs;
            m[sub] = mn;
#pragma unroll
            for (int dt = 0; dt < 8; dt++) {
                o[dt][2 * sub]     *= alpha;
                o[dt][2 * sub + 1] *= alpha;
            }
        }

        // ---- pack P directly into A fragments (NO SMEM round-trip) ----
        unsigned pa[4][4];
#pragma unroll
        for (int ks = 0; ks < 4; ks++) {
            pa[ks][0] = pack_h2(s[2*ks][0],   s[2*ks][1]);
            pa[ks][1] = pack_h2(s[2*ks][2],   s[2*ks][3]);
            pa[ks][2] = pack_h2(s[2*ks+1][0], s[2*ks+1][1]);
            pa[ks][3] = pack_h2(s[2*ks+1][2], s[2*ks+1][3]);
        }

        // ---- O += P * V (fp16, V hi+lo), skip masked kv16-slices ----
        int ksmax = (maskv && t == tdiag) ? ((warp & 3) + 1) : 4;
#pragma unroll
        for (int ks = 0; ks < 4; ks++) {
            if (ks >= ksmax) break;
#pragma unroll
            for (int dt = 0; dt < 8; dt++) {
                int d = dt * 8 + r8;
                unsigned bh0 = smw[FV_H + (ks * 8 + lq) * PW + d];
                unsigned bh1 = smw[FV_H + (ks * 8 + lq + 4) * PW + d];
                unsigned bl0 = smw[FV_L + (ks * 8 + lq) * PW + d];
                unsigned bl1 = smw[FV_L + (ks * 8 + lq + 4) * PW + d];
                mma16h(o[dt], pa[ks][0], pa[ks][1], pa[ks][2], pa[ks][3], bh0, bh1);
                mma16h(o[dt], pa[ks][0], pa[ks][1], pa[ks][2], pa[ks][3], bl0, bl1);
            }
        }
    }

    // ---- epilogue: attn[b, q, h, d] = O / l ----
    float i0 = 1.f / l[0];
    float i1 = 1.f / l[1];
    int rg = q0 + rl;
    size_t ob  = (((size_t)b * SEQL + rg) * NHEAD + h) * DKH;
    size_t ob2 = (((size_t)b * SEQL + rg + 8) * NHEAD + h) * DKH;
#pragma unroll
    for (int dt = 0; dt < 8; dt++) {
        int c = dt * 8 + lq * 2;
        g_attn[ob + c]      = o[dt][0] * i0;
        g_attn[ob + c + 1]  = o[dt][1] * i0;
        g_attn[ob2 + c]     = o[dt][2] * i1;
        g_attn[ob2 + c + 1] = o[dt][3] * i1;
    }
}

// ---------------- launcher ---------------------------------------------------
extern "C" void kernel_launch(void* const* d_in, const int* in_sizes, int n_in,
                              void* d_out, int out_size)
{
    const float* x_q = (const float*)d_in[0];
    const float* x_k = (const float*)d_in[1];
    const float* x_v = (const float*)d_in[2];
    const float* w_q = (const float*)d_in[3];
    const float* w_k = (const float*)d_in[4];
    const float* w_v = (const float*)d_in[5];
    const float* w_o = (const float*)d_in[6];
    const int*   msk = (const int*)d_in[7];
    float* out = (float*)d_out;

    cudaFuncSetAttribute((const void*)gemm_h_kernel<0,3>, cudaFuncAttributeMaxDynamicSharedMemorySize, GSM_BYTES);
    cudaFuncSetAttribute((const void*)gemm_h_kernel<0,2>, cudaFuncAttributeMaxDynamicSharedMemorySize, GSM_BYTES);
    cudaFuncSetAttribute((const void*)gemm_h_kernel<1,2>, cudaFuncAttributeMaxDynamicSharedMemorySize, GSM_BYTES);
    cudaFuncSetAttribute((const void*)flash_kernel, cudaFuncAttributeMaxDynamicSharedMemorySize, FSM_BYTES);

    // Q, K projections: fp16 x3 (score path needs precision)
    gemm_h_kernel<0,3><<<dim3(MROWS / 128, NHEAD, 2), 256, GSM_BYTES>>>(
        x_q, x_k, x_v, w_q, w_k, w_v, nullptr, 0);
    // V projection: fp16 x2
    gemm_h_kernel<0,2><<<dim3(MROWS / 128, NHEAD, 1), 256, GSM_BYTES>>>(
        x_q, x_k, x_v, w_q, w_k, w_v, nullptr, 2);

    flash_kernel<<<dim3(SEQL / 128, BATCHN * NHEAD), 256, FSM_BYTES>>>(msk);

    // Output projection: fp16 x2
    gemm_h_kernel<1,2><<<dim3(MROWS / 128, EMB / 64, 1), 256, GSM_BYTES>>>(
        nullptr, nullptr, nullptr, w_o, nullptr, nullptr, out, 0);
}

// round 9
// speedup vs baseline: 3.1085x; 1.1991x over previous
#include <cuda_runtime.h>
#include <cuda_fp16.h>
#include <cstdint>

#define BATCHN 4
#define SEQL   2048
#define EMB    1024
#define NHEAD  16
#define DKH    64
#define MROWS  (BATCHN*SEQL)   /* 8192 */

// ---------------- scratch (static device globals; no runtime allocation) ----
__device__ float g_q[(size_t)BATCHN*NHEAD*SEQL*DKH];     // [b,h,s,d]
__device__ float g_k[(size_t)BATCHN*NHEAD*SEQL*DKH];
__device__ float g_v[(size_t)BATCHN*NHEAD*SEQL*DKH];
__device__ float g_attn[(size_t)MROWS*EMB];              // [b,s,h*d]

// ---------------- helpers ---------------------------------------------------
__device__ __forceinline__ void mma16h(float c[4], unsigned a0, unsigned a1, unsigned a2, unsigned a3,
                                       unsigned b0, unsigned b1) {
    asm volatile(
        "mma.sync.aligned.m16n8k16.row.col.f32.f16.f16.f32 "
        "{%0,%1,%2,%3},{%4,%5,%6,%7},{%8,%9},{%0,%1,%2,%3};\n"
        : "+f"(c[0]), "+f"(c[1]), "+f"(c[2]), "+f"(c[3])
        : "r"(a0), "r"(a1), "r"(a2), "r"(a3), "r"(b0), "r"(b1));
}
__device__ __forceinline__ void split_h2(float x0, float x1, unsigned &hi, unsigned &lo) {
    __half2 H = __floats2half2_rn(x0, x1);
    float2 f = __half22float2(H);
    __half2 L = __floats2half2_rn(x0 - f.x, x1 - f.y);
    hi = *reinterpret_cast<unsigned*>(&H);
    lo = *reinterpret_cast<unsigned*>(&L);
}
__device__ __forceinline__ unsigned pack_h2(float x0, float x1) {
    __half2 H = __floats2half2_rn(x0, x1);
    return *reinterpret_cast<unsigned*>(&H);
}

// ---------------- GEMM (FP16 split, m16n8k16, BN=128, double-buffered) ------
// A tile: [128 rows][AW=20 kpair words] hi/lo.  B tile: [16 kpairs][BW=136] hi/lo.
// Warp grid 4m x 2n; warp tile 32 x 64 (mt 0..1, nt 0..7).
// MODE 0: projections, 2 heads per CTA (y = head pair, z + selbase = q/k/v).
// MODE 1: output projection (y = 128-col block).
#define AW 20
#define BW 136
#define G_AH 0
#define G_AL (128*AW)
#define G_BH (2*128*AW)
#define G_BL (2*128*AW + 16*BW)
#define GSTAGE (2*128*AW + 2*16*BW)      /* 9472 words */
#define GSM_BYTES (2*GSTAGE*4)           /* 75776 bytes */

template<int MODE, int PASSES>
__global__ void __launch_bounds__(256, 2) gemm_h_kernel(
    const float* __restrict__ A0, const float* __restrict__ A1, const float* __restrict__ A2,
    const float* __restrict__ B0, const float* __restrict__ B1, const float* __restrict__ B2,
    float* __restrict__ Cext, int selbase)
{
    extern __shared__ unsigned smu[];

    const int tid  = threadIdx.x;
    const int lane = tid & 31;
    const int warp = tid >> 5;
    const int wm = warp >> 1, wn = warp & 1;
    const int r8 = lane >> 2, lq = lane & 3;
    const int row0 = blockIdx.x * 128;

    const float* A;
    const float* Bt;   // base of weight block for this CTA's 128 columns
    int ldb;
    float* Cq;
    if (MODE == 0) {
        int sel = blockIdx.z + selbase;
        A = sel == 0 ? A0 : (sel == 1 ? A1 : A2);
        const float* W = sel == 0 ? B0 : (sel == 1 ? B1 : B2);
        Bt = W + (size_t)(blockIdx.y * 2) * EMB * 64;   // head pair base
        ldb = 64;
        Cq = sel == 0 ? g_q : (sel == 1 ? g_k : g_v);
    } else {
        A = g_attn; Bt = B0 + blockIdx.y * 128; ldb = EMB; Cq = Cext;
    }

    float acc[2][8][4];
#pragma unroll
    for (int i = 0; i < 2; i++)
#pragma unroll
        for (int j = 0; j < 8; j++)
#pragma unroll
            for (int r = 0; r < 4; r++) acc[i][j][r] = 0.f;

    // producer mappings
    const int am   = tid & 127;          // A row
    const int akh  = (tid >> 7) * 16;    // A k-offset (16 elems)
    const int bn   = tid & 127;          // B col (0..127)
    const int bk2g = (tid >> 7) * 8;     // B first kpair (8 kpairs per thread)

    // column address helper (MODE 0 spans two heads)
    size_t bcol;
    if (MODE == 0) bcol = (size_t)(bn >> 6) * EMB * 64 + (bn & 63);
    else           bcol = bn;

    float4 ra[4];
    float  rbv[16];

    // prologue: load + split + store chunk 0 into stage 0
#pragma unroll
    for (int i = 0; i < 4; i++)
        ra[i] = *reinterpret_cast<const float4*>(A + (size_t)(row0 + am) * EMB + akh + i * 4);
#pragma unroll
    for (int j = 0; j < 8; j++) {
        rbv[2*j]   = Bt[(size_t)(2 * (bk2g + j)) * ldb + bcol];
        rbv[2*j+1] = Bt[(size_t)(2 * (bk2g + j) + 1) * ldb + bcol];
    }
    {
        unsigned hw[8], lw[8];
#pragma unroll
        for (int i = 0; i < 4; i++) {
            split_h2(ra[i].x, ra[i].y, hw[2*i],   lw[2*i]);
            split_h2(ra[i].z, ra[i].w, hw[2*i+1], lw[2*i+1]);
        }
        int base = am * AW + (akh >> 1);
        *reinterpret_cast<uint4*>(smu + G_AH + base)     = make_uint4(hw[0], hw[1], hw[2], hw[3]);
        *reinterpret_cast<uint4*>(smu + G_AH + base + 4) = make_uint4(hw[4], hw[5], hw[6], hw[7]);
        *reinterpret_cast<uint4*>(smu + G_AL + base)     = make_uint4(lw[0], lw[1], lw[2], lw[3]);
        *reinterpret_cast<uint4*>(smu + G_AL + base + 4) = make_uint4(lw[4], lw[5], lw[6], lw[7]);
#pragma unroll
        for (int j = 0; j < 8; j++) {
            unsigned bh, bl;
            split_h2(rbv[2*j], rbv[2*j+1], bh, bl);
            smu[G_BH + (bk2g + j) * BW + bn] = bh;
            smu[G_BL + (bk2g + j) * BW + bn] = bl;
        }
    }
    __syncthreads();

    for (int c = 0; c < EMB / 32; c++) {
        const int st = c & 1;
        unsigned* Ah2 = smu + st * GSTAGE + G_AH;
        unsigned* Al2 = smu + st * GSTAGE + G_AL;
        unsigned* Bh2 = smu + st * GSTAGE + G_BH;
        unsigned* Bl2 = smu + st * GSTAGE + G_BL;

        const bool more = (c + 1 < EMB / 32);
        if (more) {
            int k0 = (c + 1) * 32;
#pragma unroll
            for (int i = 0; i < 4; i++)
                ra[i] = *reinterpret_cast<const float4*>(A + (size_t)(row0 + am) * EMB + k0 + akh + i * 4);
#pragma unroll
            for (int j = 0; j < 8; j++) {
                rbv[2*j]   = Bt[(size_t)(k0 + 2 * (bk2g + j)) * ldb + bcol];
                rbv[2*j+1] = Bt[(size_t)(k0 + 2 * (bk2g + j) + 1) * ldb + bcol];
            }
        }

        // ---- compute from stage st ----
#pragma unroll
        for (int ks = 0; ks < 2; ks++) {
            const int kw = ks * 8;
            unsigned ah[2][4], al[2][4];
#pragma unroll
            for (int mt = 0; mt < 2; mt++) {
                int rw = (wm * 32 + mt * 16 + r8) * AW + kw + lq;
                ah[mt][0] = Ah2[rw];              al[mt][0] = Al2[rw];
                ah[mt][1] = Ah2[rw + 8 * AW];     al[mt][1] = Al2[rw + 8 * AW];
                ah[mt][2] = Ah2[rw + 4];          al[mt][2] = Al2[rw + 4];
                ah[mt][3] = Ah2[rw + 8 * AW + 4]; al[mt][3] = Al2[rw + 8 * AW + 4];
            }
#pragma unroll
            for (int nt = 0; nt < 8; nt++) {
                int n = wn * 64 + nt * 8 + r8;
                unsigned bh0 = Bh2[(kw + lq) * BW + n];
                unsigned bh1 = Bh2[(kw + 4 + lq) * BW + n];
#pragma unroll
                for (int mt = 0; mt < 2; mt++) {
                    mma16h(acc[mt][nt], ah[mt][0], ah[mt][1], ah[mt][2], ah[mt][3], bh0, bh1);
                    if (PASSES >= 2)
                        mma16h(acc[mt][nt], al[mt][0], al[mt][1], al[mt][2], al[mt][3], bh0, bh1);
                }
                if (PASSES >= 3) {
                    unsigned bl0 = Bl2[(kw + lq) * BW + n];
                    unsigned bl1 = Bl2[(kw + 4 + lq) * BW + n];
#pragma unroll
                    for (int mt = 0; mt < 2; mt++)
                        mma16h(acc[mt][nt], ah[mt][0], ah[mt][1], ah[mt][2], ah[mt][3], bl0, bl1);
                }
            }
        }

        // ---- store chunk c+1 into stage st^1 ----
        if (more) {
            unsigned* Ah2n = smu + (st ^ 1) * GSTAGE + G_AH;
            unsigned* Al2n = smu + (st ^ 1) * GSTAGE + G_AL;
            unsigned* Bh2n = smu + (st ^ 1) * GSTAGE + G_BH;
            unsigned* Bl2n = smu + (st ^ 1) * GSTAGE + G_BL;
            unsigned hw[8], lw[8];
#pragma unroll
            for (int i = 0; i < 4; i++) {
                split_h2(ra[i].x, ra[i].y, hw[2*i],   lw[2*i]);
                split_h2(ra[i].z, ra[i].w, hw[2*i+1], lw[2*i+1]);
            }
            int base = am * AW + (akh >> 1);
            *reinterpret_cast<uint4*>(Ah2n + base)     = make_uint4(hw[0], hw[1], hw[2], hw[3]);
            *reinterpret_cast<uint4*>(Ah2n + base + 4) = make_uint4(hw[4], hw[5], hw[6], hw[7]);
            *reinterpret_cast<uint4*>(Al2n + base)     = make_uint4(lw[0], lw[1], lw[2], lw[3]);
            *reinterpret_cast<uint4*>(Al2n + base + 4) = make_uint4(lw[4], lw[5], lw[6], lw[7]);
#pragma unroll
            for (int j = 0; j < 8; j++) {
                unsigned bh, bl;
                split_h2(rbv[2*j], rbv[2*j+1], bh, bl);
                Bh2n[(bk2g + j) * BW + bn] = bh;
                Bl2n[(bk2g + j) * BW + bn] = bl;
            }
        }
        __syncthreads();
    }

    // ---- epilogue ----
#pragma unroll
    for (int mt = 0; mt < 2; mt++) {
        int r = row0 + wm * 32 + mt * 16 + r8;
#pragma unroll
        for (int nt = 0; nt < 8; nt++) {
            int cc = wn * 64 + nt * 8 + lq * 2;
            if (MODE == 0) {
                int b = r >> 11, s = r & 2047;
                int head = blockIdx.y * 2 + (cc >> 6);
                int d = cc & 63;
                size_t base  = (((size_t)b * NHEAD + head) * SEQL + s) * DKH + d;
                size_t base2 = base + (size_t)8 * DKH;
                Cq[base]      = acc[mt][nt][0];
                Cq[base + 1]  = acc[mt][nt][1];
                Cq[base2]     = acc[mt][nt][2];
                Cq[base2 + 1] = acc[mt][nt][3];
            } else {
                size_t base = (size_t)r * EMB + blockIdx.y * 128 + cc;
                Cq[base]               = acc[mt][nt][0];
                Cq[base + 1]           = acc[mt][nt][1];
                Cq[base + 8 * EMB]     = acc[mt][nt][2];
                Cq[base + 8 * EMB + 1] = acc[mt][nt][3];
            }
        }
    }
}

// ---------------- flash attention (causal), full fp16 split — as R8 ----------
#define QW 36
#define KW 36
#define PW 68
#define FQ_H 0
#define FQ_L (128*QW)
#define FK_H 0
#define FK_L (64*KW)
#define FV_H (2*64*KW)
#define FV_L (2*64*KW + 32*PW)
#define FSM_WORDS (2*128*QW)
#define FSM_BYTES (FSM_WORDS*4)
#define LOG2E 1.4426950408889634f

__global__ void __launch_bounds__(256) flash_kernel(const int* __restrict__ maskp)
{
    extern __shared__ unsigned smw[];

    const int tid  = threadIdx.x;
    const int lane = tid & 31;
    const int warp = tid >> 5;
    const int r8 = lane >> 2, lq = lane & 3;
    const int qt = blockIdx.x;
    const int bh = blockIdx.y;
    const int b = bh >> 4, h = bh & 15;
    const int q0 = qt * 128;

    const float* Q = g_q + (size_t)bh * SEQL * DKH;
    const float* K = g_k + (size_t)bh * SEQL * DKH;
    const float* V = g_v + (size_t)bh * SEQL * DKH;

    const float qscale = 8.f * LOG2E;
#pragma unroll
    for (int ii = 0; ii < 8; ii++) {
        int i = tid + ii * 256;
        int r = i >> 4, c4 = (i & 15) << 2;
        float4 v4 = *reinterpret_cast<const float4*>(Q + (size_t)(q0 + r) * DKH + c4);
        unsigned h01, l01, h23, l23;
        split_h2(v4.x * qscale, v4.y * qscale, h01, l01);
        split_h2(v4.z * qscale, v4.w * qscale, h23, l23);
        int base = r * QW + (c4 >> 1);
        *reinterpret_cast<uint2*>(smw + FQ_H + base) = make_uint2(h01, h23);
        *reinterpret_cast<uint2*>(smw + FQ_L + base) = make_uint2(l01, l23);
    }
    __syncthreads();

    const int rl = warp * 16 + r8;
    unsigned qh[4][4], ql[4][4];
#pragma unroll
    for (int ks = 0; ks < 4; ks++) {
        int base = rl * QW + ks * 8 + lq;
        qh[ks][0] = smw[FQ_H + base];
        qh[ks][1] = smw[FQ_H + base + 8 * QW];
        qh[ks][2] = smw[FQ_H + base + 4];
        qh[ks][3] = smw[FQ_H + base + 8 * QW + 4];
        ql[ks][0] = smw[FQ_L + base];
        ql[ks][1] = smw[FQ_L + base + 8 * QW];
        ql[ks][2] = smw[FQ_L + base + 4];
        ql[ks][3] = smw[FQ_L + base + 8 * QW + 4];
    }
    __syncthreads();

    float m[2] = { -1e30f, -1e30f };
    float l[2] = { 0.f, 0.f };
    float o[8][4];
#pragma unroll
    for (int i = 0; i < 8; i++)
#pragma unroll
        for (int j = 0; j < 4; j++) o[i][j] = 0.f;

    const int maskv = maskp[0];
    const int tdiag = 2 * qt + (warp >> 2);
    const int ntiles = maskv ? (2 * qt + 2) : (SEQL / 64);

    __half* vhp = reinterpret_cast<__half*>(smw + FV_H);
    __half* vlp = reinterpret_cast<__half*>(smw + FV_L);

    for (int t = 0; t < ntiles; t++) {
        const int kv0 = t * 64;

        if (t > 0) __syncthreads();
#pragma unroll
        for (int ii = 0; ii < 4; ii++) {
            int i = tid + ii * 256;
            int r = i >> 4, c4 = (i & 15) << 2;
            float4 k4 = *reinterpret_cast<const float4*>(K + (size_t)(kv0 + r) * DKH + c4);
            unsigned h01, l01, h23, l23;
            split_h2(k4.x, k4.y, h01, l01);
            split_h2(k4.z, k4.w, h23, l23);
            int kb = r * KW + (c4 >> 1);
            *reinterpret_cast<uint2*>(smw + FK_H + kb) = make_uint2(h01, h23);
            *reinterpret_cast<uint2*>(smw + FK_L + kb) = make_uint2(l01, l23);

            float4 v4 = *reinterpret_cast<const float4*>(V + (size_t)(kv0 + r) * DKH + c4);
            float vv[4] = { v4.x, v4.y, v4.z, v4.w };
            int p = r >> 1, rb = r & 1;
#pragma unroll
            for (int j = 0; j < 4; j++) {
                __half hv = __float2half_rn(vv[j]);
                __half lv = __float2half_rn(vv[j] - __half2float(hv));
                int hidx = (p * PW + c4 + j) * 2 + rb;
                vhp[hidx] = hv;
                vlp[hidx] = lv;
            }
        }
        __syncthreads();

        if (maskv && t > tdiag) continue;

        float s[8][4];
#pragma unroll
        for (int i = 0; i < 8; i++)
#pragma unroll
            for (int j = 0; j < 4; j++) s[i][j] = 0.f;

#pragma unroll
        for (int ks = 0; ks < 4; ks++) {
#pragma unroll
            for (int nt = 0; nt < 8; nt++) {
                int n = nt * 8 + r8;
                unsigned bh0 = smw[FK_H + n * KW + ks * 8 + lq];
                unsigned bh1 = smw[FK_H + n * KW + ks * 8 + lq + 4];
                unsigned bl0 = smw[FK_L + n * KW + ks * 8 + lq];
                unsigned bl1 = smw[FK_L + n * KW + ks * 8 + lq + 4];
                mma16h(s[nt], qh[ks][0], qh[ks][1], qh[ks][2], qh[ks][3], bh0, bh1);
                mma16h(s[nt], qh[ks][0], qh[ks][1], qh[ks][2], qh[ks][3], bl0, bl1);
                mma16h(s[nt], ql[ks][0], ql[ks][1], ql[ks][2], ql[ks][3], bh0, bh1);
            }
        }

        if (maskv && t == tdiag) {
            int rg0 = q0 + rl;
#pragma unroll
            for (int nt = 0; nt < 8; nt++) {
                int cg = kv0 + nt * 8 + lq * 2;
                if (cg > rg0)         s[nt][0] = -1e30f;
                if (cg + 1 > rg0)     s[nt][1] = -1e30f;
                if (cg > rg0 + 8)     s[nt][2] = -1e30f;
                if (cg + 1 > rg0 + 8) s[nt][3] = -1e30f;
            }
        }

#pragma unroll
        for (int sub = 0; sub < 2; sub++) {
            float tm = -1e30f;
#pragma unroll
            for (int nt = 0; nt < 8; nt++)
                tm = fmaxf(tm, fmaxf(s[nt][2 * sub], s[nt][2 * sub + 1]));
            tm = fmaxf(tm, __shfl_xor_sync(0xffffffffu, tm, 1));
            tm = fmaxf(tm, __shfl_xor_sync(0xffffffffu, tm, 2));
            float mn = fmaxf(m[sub], tm);
            float alpha = exp2f(m[sub] - mn);
            float rs = 0.f;
#pragma unroll
            for (int nt = 0; nt < 8; nt++) {
                float p0 = exp2f(s[nt][2 * sub] - mn);
                float p1 = exp2f(s[nt][2 * sub + 1] - mn);
                s[nt][2 * sub] = p0; s[nt][2 * sub + 1] = p1;
                rs += p0 + p1;
            }
            rs += __shfl_xor_sync(0xffffffffu, rs, 1);
            rs += __shfl_xor_sync(0xffffffffu, rs, 2);
            l[sub] = l[sub] * alpha + rs;
            m[sub] = mn;
#pragma unroll
            for (int dt = 0; dt < 8; dt++) {
                o[dt][2 * sub]     *= alpha;
                o[dt][2 * sub + 1] *= alpha;
            }
        }

        unsigned pa[4][4];
#pragma unroll
        for (int ks = 0; ks < 4; ks++) {
            pa[ks][0] = pack_h2(s[2*ks][0],   s[2*ks][1]);
            pa[ks][1] = pack_h2(s[2*ks][2],   s[2*ks][3]);
            pa[ks][2] = pack_h2(s[2*ks+1][0], s[2*ks+1][1]);
            pa[ks][3] = pack_h2(s[2*ks+1][2], s[2*ks+1][3]);
        }

        int ksmax = (maskv && t == tdiag) ? ((warp & 3) + 1) : 4;
#pragma unroll
        for (int ks = 0; ks < 4; ks++) {
            if (ks >= ksmax) break;
#pragma unroll
            for (int dt = 0; dt < 8; dt++) {
                int d = dt * 8 + r8;
                unsigned bh0 = smw[FV_H + (ks * 8 + lq) * PW + d];
                unsigned bh1 = smw[FV_H + (ks * 8 + lq + 4) * PW + d];
                unsigned bl0 = smw[FV_L + (ks * 8 + lq) * PW + d];
                unsigned bl1 = smw[FV_L + (ks * 8 + lq + 4) * PW + d];
                mma16h(o[dt], pa[ks][0], pa[ks][1], pa[ks][2], pa[ks][3], bh0, bh1);
                mma16h(o[dt], pa[ks][0], pa[ks][1], pa[ks][2], pa[ks][3], bl0, bl1);
            }
        }
    }

    float i0 = 1.f / l[0];
    float i1 = 1.f / l[1];
    int rg = q0 + rl;
    size_t ob  = (((size_t)b * SEQL + rg) * NHEAD + h) * DKH;
    size_t ob2 = (((size_t)b * SEQL + rg + 8) * NHEAD + h) * DKH;
#pragma unroll
    for (int dt = 0; dt < 8; dt++) {
        int c = dt * 8 + lq * 2;
        g_attn[ob + c]      = o[dt][0] * i0;
        g_attn[ob + c + 1]  = o[dt][1] * i0;
        g_attn[ob2 + c]     = o[dt][2] * i1;
        g_attn[ob2 + c + 1] = o[dt][3] * i1;
    }
}

// ---------------- launcher ---------------------------------------------------
extern "C" void kernel_launch(void* const* d_in, const int* in_sizes, int n_in,
                              void* d_out, int out_size)
{
    const float* x_q = (const float*)d_in[0];
    const float* x_k = (const float*)d_in[1];
    const float* x_v = (const float*)d_in[2];
    const float* w_q = (const float*)d_in[3];
    const float* w_k = (const float*)d_in[4];
    const float* w_v = (const float*)d_in[5];
    const float* w_o = (const float*)d_in[6];
    const int*   msk = (const int*)d_in[7];
    float* out = (float*)d_out;

    cudaFuncSetAttribute((const void*)gemm_h_kernel<0,3>, cudaFuncAttributeMaxDynamicSharedMemorySize, GSM_BYTES);
    cudaFuncSetAttribute((const void*)gemm_h_kernel<0,2>, cudaFuncAttributeMaxDynamicSharedMemorySize, GSM_BYTES);
    cudaFuncSetAttribute((const void*)gemm_h_kernel<1,2>, cudaFuncAttributeMaxDynamicSharedMemorySize, GSM_BYTES);
    cudaFuncSetAttribute((const void*)flash_kernel, cudaFuncAttributeMaxDynamicSharedMemorySize, FSM_BYTES);

    // Q, K projections: fp16 x3, 2 heads per CTA
    gemm_h_kernel<0,3><<<dim3(MROWS / 128, NHEAD / 2, 2), 256, GSM_BYTES>>>(
        x_q, x_k, x_v, w_q, w_k, w_v, nullptr, 0);
    // V projection: fp16 x2
    gemm_h_kernel<0,2><<<dim3(MROWS / 128, NHEAD / 2, 1), 256, GSM_BYTES>>>(
        x_q, x_k, x_v, w_q, w_k, w_v, nullptr, 2);

    flash_kernel<<<dim3(SEQL / 128, BATCHN * NHEAD), 256, FSM_BYTES>>>(msk);

    // Output projection: fp16 x2
    gemm_h_kernel<1,2><<<dim3(MROWS / 128, EMB / 128, 1), 256, GSM_BYTES>>>(
        nullptr, nullptr, nullptr, w_o, nullptr, nullptr, out, 0);
}

// round 10
// speedup vs baseline: 3.1785x; 1.0225x over previous
#include <cuda_runtime.h>
#include <cuda_fp16.h>
#include <cstdint>

#define BATCHN 4
#define SEQL   2048
#define EMB    1024
#define NHEAD  16
#define DKH    64
#define MROWS  (BATCHN*SEQL)   /* 8192 */

// ---------------- scratch (static device globals; no runtime allocation) ----
__device__ float g_q[(size_t)BATCHN*NHEAD*SEQL*DKH];     // [b,h,s,d]
__device__ float g_k[(size_t)BATCHN*NHEAD*SEQL*DKH];
__device__ float g_v[(size_t)BATCHN*NHEAD*SEQL*DKH];
__device__ float g_attn[(size_t)MROWS*EMB];              // [b,s,h*d]

// ---------------- helpers ---------------------------------------------------
__device__ __forceinline__ void mma16h(float c[4], unsigned a0, unsigned a1, unsigned a2, unsigned a3,
                                       unsigned b0, unsigned b1) {
    asm volatile(
        "mma.sync.aligned.m16n8k16.row.col.f32.f16.f16.f32 "
        "{%0,%1,%2,%3},{%4,%5,%6,%7},{%8,%9},{%0,%1,%2,%3};\n"
        : "+f"(c[0]), "+f"(c[1]), "+f"(c[2]), "+f"(c[3])
        : "r"(a0), "r"(a1), "r"(a2), "r"(a3), "r"(b0), "r"(b1));
}
__device__ __forceinline__ void split_h2(float x0, float x1, unsigned &hi, unsigned &lo) {
    __half2 H = __floats2half2_rn(x0, x1);
    float2 f = __half22float2(H);
    __half2 L = __floats2half2_rn(x0 - f.x, x1 - f.y);
    hi = *reinterpret_cast<unsigned*>(&H);
    lo = *reinterpret_cast<unsigned*>(&L);
}
__device__ __forceinline__ unsigned pack_h2(float x0, float x1) {
    __half2 H = __floats2half2_rn(x0, x1);
    return *reinterpret_cast<unsigned*>(&H);
}

// ---------------- GEMM (FP16 split, m16n8k16, BN=128, double-buffered) ------
// A tile: [128 rows][AW=20 kpair words] hi/lo.  B tile: [16 kpairs][BW=136] hi/lo.
// B producer: per thread 2 assignments x 2 rows of float4 (all LDG.128).
#define AW 20
#define BW 136
#define G_AH 0
#define G_AL (128*AW)
#define G_BH (2*128*AW)
#define G_BL (2*128*AW + 16*BW)
#define GSTAGE (2*128*AW + 2*16*BW)      /* 9472 words */
#define GSM_BYTES (2*GSTAGE*4)           /* 75776 bytes */

template<int MODE, int PASSES>
__global__ void __launch_bounds__(256, 2) gemm_h_kernel(
    const float* __restrict__ A0, const float* __restrict__ A1, const float* __restrict__ A2,
    const float* __restrict__ B0, const float* __restrict__ B1, const float* __restrict__ B2,
    float* __restrict__ Cext, int selbase)
{
    extern __shared__ unsigned smu[];

    const int tid  = threadIdx.x;
    const int lane = tid & 31;
    const int warp = tid >> 5;
    const int wm = warp >> 1, wn = warp & 1;
    const int r8 = lane >> 2, lq = lane & 3;
    const int row0 = blockIdx.x * 128;

    const float* A;
    const float* Bt;
    int ldb;
    float* Cq;
    if (MODE == 0) {
        int sel = blockIdx.z + selbase;
        A = sel == 0 ? A0 : (sel == 1 ? A1 : A2);
        const float* W = sel == 0 ? B0 : (sel == 1 ? B1 : B2);
        Bt = W + (size_t)(blockIdx.y * 2) * EMB * 64;
        ldb = 64;
        Cq = sel == 0 ? g_q : (sel == 1 ? g_k : g_v);
    } else {
        A = g_attn; Bt = B0 + blockIdx.y * 128; ldb = EMB; Cq = Cext;
    }

    float acc[2][8][4];
#pragma unroll
    for (int i = 0; i < 2; i++)
#pragma unroll
        for (int j = 0; j < 8; j++)
#pragma unroll
            for (int r = 0; r < 4; r++) acc[i][j][r] = 0.f;

    // producer mappings
    const int am  = tid & 127;            // A row
    const int akh = (tid >> 7) * 16;      // A k-offset (16 elems)
    // B: assignment a in {0,1}: g = tid + a*256; kpair p = g>>5; col c = (g&31)*4
    int bp[2], bc[2];
    size_t bcol[2];
#pragma unroll
    for (int a = 0; a < 2; a++) {
        int g = tid + a * 256;
        bp[a] = g >> 5;
        bc[a] = (g & 31) * 4;
        bcol[a] = (MODE == 0) ? ((size_t)(bc[a] >> 6) * EMB * 64 + (bc[a] & 63))
                              : (size_t)bc[a];
    }

    float4 ra[4];
    float4 rb0[2], rb1[2];   // per assignment: even-k row, odd-k row

    // prologue: load + split + store chunk 0 into stage 0
#pragma unroll
    for (int i = 0; i < 4; i++)
        ra[i] = *reinterpret_cast<const float4*>(A + (size_t)(row0 + am) * EMB + akh + i * 4);
#pragma unroll
    for (int a = 0; a < 2; a++) {
        rb0[a] = *reinterpret_cast<const float4*>(Bt + (size_t)(2 * bp[a]) * ldb + bcol[a]);
        rb1[a] = *reinterpret_cast<const float4*>(Bt + (size_t)(2 * bp[a] + 1) * ldb + bcol[a]);
    }
    {
        unsigned hw[8], lw[8];
#pragma unroll
        for (int i = 0; i < 4; i++) {
            split_h2(ra[i].x, ra[i].y, hw[2*i],   lw[2*i]);
            split_h2(ra[i].z, ra[i].w, hw[2*i+1], lw[2*i+1]);
        }
        int base = am * AW + (akh >> 1);
        *reinterpret_cast<uint4*>(smu + G_AH + base)     = make_uint4(hw[0], hw[1], hw[2], hw[3]);
        *reinterpret_cast<uint4*>(smu + G_AH + base + 4) = make_uint4(hw[4], hw[5], hw[6], hw[7]);
        *reinterpret_cast<uint4*>(smu + G_AL + base)     = make_uint4(lw[0], lw[1], lw[2], lw[3]);
        *reinterpret_cast<uint4*>(smu + G_AL + base + 4) = make_uint4(lw[4], lw[5], lw[6], lw[7]);
#pragma unroll
        for (int a = 0; a < 2; a++) {
            unsigned bh[4], bl[4];
            split_h2(rb0[a].x, rb1[a].x, bh[0], bl[0]);
            split_h2(rb0[a].y, rb1[a].y, bh[1], bl[1]);
            split_h2(rb0[a].z, rb1[a].z, bh[2], bl[2]);
            split_h2(rb0[a].w, rb1[a].w, bh[3], bl[3]);
            *reinterpret_cast<uint4*>(smu + G_BH + bp[a] * BW + bc[a]) =
                make_uint4(bh[0], bh[1], bh[2], bh[3]);
            if (PASSES >= 3)
                *reinterpret_cast<uint4*>(smu + G_BL + bp[a] * BW + bc[a]) =
                    make_uint4(bl[0], bl[1], bl[2], bl[3]);
        }
    }
    __syncthreads();

    for (int c = 0; c < EMB / 32; c++) {
        const int st = c & 1;
        unsigned* Ah2 = smu + st * GSTAGE + G_AH;
        unsigned* Al2 = smu + st * GSTAGE + G_AL;
        unsigned* Bh2 = smu + st * GSTAGE + G_BH;
        unsigned* Bl2 = smu + st * GSTAGE + G_BL;

        const bool more = (c + 1 < EMB / 32);
        if (more) {
            int k0 = (c + 1) * 32;
#pragma unroll
            for (int i = 0; i < 4; i++)
                ra[i] = *reinterpret_cast<const float4*>(A + (size_t)(row0 + am) * EMB + k0 + akh + i * 4);
#pragma unroll
            for (int a = 0; a < 2; a++) {
                rb0[a] = *reinterpret_cast<const float4*>(Bt + (size_t)(k0 + 2 * bp[a]) * ldb + bcol[a]);
                rb1[a] = *reinterpret_cast<const float4*>(Bt + (size_t)(k0 + 2 * bp[a] + 1) * ldb + bcol[a]);
            }
        }

        // ---- compute from stage st ----
#pragma unroll
        for (int ks = 0; ks < 2; ks++) {
            const int kw = ks * 8;
            unsigned ah[2][4], al[2][4];
#pragma unroll
            for (int mt = 0; mt < 2; mt++) {
                int rw = (wm * 32 + mt * 16 + r8) * AW + kw + lq;
                ah[mt][0] = Ah2[rw];              al[mt][0] = Al2[rw];
                ah[mt][1] = Ah2[rw + 8 * AW];     al[mt][1] = Al2[rw + 8 * AW];
                ah[mt][2] = Ah2[rw + 4];          al[mt][2] = Al2[rw + 4];
                ah[mt][3] = Ah2[rw + 8 * AW + 4]; al[mt][3] = Al2[rw + 8 * AW + 4];
            }
#pragma unroll
            for (int nt = 0; nt < 8; nt++) {
                int n = wn * 64 + nt * 8 + r8;
                unsigned bh0 = Bh2[(kw + lq) * BW + n];
                unsigned bh1 = Bh2[(kw + 4 + lq) * BW + n];
#pragma unroll
                for (int mt = 0; mt < 2; mt++) {
                    mma16h(acc[mt][nt], ah[mt][0], ah[mt][1], ah[mt][2], ah[mt][3], bh0, bh1);
                    if (PASSES >= 2)
                        mma16h(acc[mt][nt], al[mt][0], al[mt][1], al[mt][2], al[mt][3], bh0, bh1);
                }
                if (PASSES >= 3) {
                    unsigned bl0 = Bl2[(kw + lq) * BW + n];
                    unsigned bl1 = Bl2[(kw + 4 + lq) * BW + n];
#pragma unroll
                    for (int mt = 0; mt < 2; mt++)
                        mma16h(acc[mt][nt], ah[mt][0], ah[mt][1], ah[mt][2], ah[mt][3], bl0, bl1);
                }
            }
        }

        // ---- store chunk c+1 into stage st^1 ----
        if (more) {
            unsigned* Ah2n = smu + (st ^ 1) * GSTAGE + G_AH;
            unsigned* Al2n = smu + (st ^ 1) * GSTAGE + G_AL;
            unsigned* Bh2n = smu + (st ^ 1) * GSTAGE + G_BH;
            unsigned* Bl2n = smu + (st ^ 1) * GSTAGE + G_BL;
            unsigned hw[8], lw[8];
#pragma unroll
            for (int i = 0; i < 4; i++) {
                split_h2(ra[i].x, ra[i].y, hw[2*i],   lw[2*i]);
                split_h2(ra[i].z, ra[i].w, hw[2*i+1], lw[2*i+1]);
            }
            int base = am * AW + (akh >> 1);
            *reinterpret_cast<uint4*>(Ah2n + base)     = make_uint4(hw[0], hw[1], hw[2], hw[3]);
            *reinterpret_cast<uint4*>(Ah2n + base + 4) = make_uint4(hw[4], hw[5], hw[6], hw[7]);
            *reinterpret_cast<uint4*>(Al2n + base)     = make_uint4(lw[0], lw[1], lw[2], lw[3]);
            *reinterpret_cast<uint4*>(Al2n + base + 4) = make_uint4(lw[4], lw[5], lw[6], lw[7]);
#pragma unroll
            for (int a = 0; a < 2; a++) {
                unsigned bh[4], bl[4];
                split_h2(rb0[a].x, rb1[a].x, bh[0], bl[0]);
                split_h2(rb0[a].y, rb1[a].y, bh[1], bl[1]);
                split_h2(rb0[a].z, rb1[a].z, bh[2], bl[2]);
                split_h2(rb0[a].w, rb1[a].w, bh[3], bl[3]);
                *reinterpret_cast<uint4*>(Bh2n + bp[a] * BW + bc[a]) =
                    make_uint4(bh[0], bh[1], bh[2], bh[3]);
                if (PASSES >= 3)
                    *reinterpret_cast<uint4*>(Bl2n + bp[a] * BW + bc[a]) =
                        make_uint4(bl[0], bl[1], bl[2], bl[3]);
            }
        }
        __syncthreads();
    }

    // ---- epilogue ----
#pragma unroll
    for (int mt = 0; mt < 2; mt++) {
        int r = row0 + wm * 32 + mt * 16 + r8;
#pragma unroll
        for (int nt = 0; nt < 8; nt++) {
            int cc = wn * 64 + nt * 8 + lq * 2;
            if (MODE == 0) {
                int b = r >> 11, s = r & 2047;
                int head = blockIdx.y * 2 + (cc >> 6);
                int d = cc & 63;
                size_t base  = (((size_t)b * NHEAD + head) * SEQL + s) * DKH + d;
                size_t base2 = base + (size_t)8 * DKH;
                Cq[base]      = acc[mt][nt][0];
                Cq[base + 1]  = acc[mt][nt][1];
                Cq[base2]     = acc[mt][nt][2];
                Cq[base2 + 1] = acc[mt][nt][3];
            } else {
                size_t base = (size_t)r * EMB + blockIdx.y * 128 + cc;
                Cq[base]               = acc[mt][nt][0];
                Cq[base + 1]           = acc[mt][nt][1];
                Cq[base + 8 * EMB]     = acc[mt][nt][2];
                Cq[base + 8 * EMB + 1] = acc[mt][nt][3];
            }
        }
    }
}

// ---------------- flash attention (causal), fp16; PV single-pass -------------
#define QW 36
#define KW 36
#define PW 68
#define FQ_H 0
#define FQ_L (128*QW)
#define FK_H 0
#define FK_L (64*KW)
#define FV_H (2*64*KW)
#define FSM_WORDS (2*128*QW)
#define FSM_BYTES (FSM_WORDS*4)
#define LOG2E 1.4426950408889634f

__global__ void __launch_bounds__(256) flash_kernel(const int* __restrict__ maskp)
{
    extern __shared__ unsigned smw[];

    const int tid  = threadIdx.x;
    const int lane = tid & 31;
    const int warp = tid >> 5;
    const int r8 = lane >> 2, lq = lane & 3;
    const int qt = blockIdx.x;
    const int bh = blockIdx.y;
    const int b = bh >> 4, h = bh & 15;
    const int q0 = qt * 128;

    const float* Q = g_q + (size_t)bh * SEQL * DKH;
    const float* K = g_k + (size_t)bh * SEQL * DKH;
    const float* V = g_v + (size_t)bh * SEQL * DKH;

    const float qscale = 8.f * LOG2E;
#pragma unroll
    for (int ii = 0; ii < 8; ii++) {
        int i = tid + ii * 256;
        int r = i >> 4, c4 = (i & 15) << 2;
        float4 v4 = *reinterpret_cast<const float4*>(Q + (size_t)(q0 + r) * DKH + c4);
        unsigned h01, l01, h23, l23;
        split_h2(v4.x * qscale, v4.y * qscale, h01, l01);
        split_h2(v4.z * qscale, v4.w * qscale, h23, l23);
        int base = r * QW + (c4 >> 1);
        *reinterpret_cast<uint2*>(smw + FQ_H + base) = make_uint2(h01, h23);
        *reinterpret_cast<uint2*>(smw + FQ_L + base) = make_uint2(l01, l23);
    }
    __syncthreads();

    const int rl = warp * 16 + r8;
    unsigned qh[4][4], ql[4][4];
#pragma unroll
    for (int ks = 0; ks < 4; ks++) {
        int base = rl * QW + ks * 8 + lq;
        qh[ks][0] = smw[FQ_H + base];
        qh[ks][1] = smw[FQ_H + base + 8 * QW];
        qh[ks][2] = smw[FQ_H + base + 4];
        qh[ks][3] = smw[FQ_H + base + 8 * QW + 4];
        ql[ks][0] = smw[FQ_L + base];
        ql[ks][1] = smw[FQ_L + base + 8 * QW];
        ql[ks][2] = smw[FQ_L + base + 4];
        ql[ks][3] = smw[FQ_L + base + 8 * QW + 4];
    }
    __syncthreads();

    float m[2] = { -1e30f, -1e30f };
    float l[2] = { 0.f, 0.f };
    float o[8][4];
#pragma unroll
    for (int i = 0; i < 8; i++)
#pragma unroll
        for (int j = 0; j < 4; j++) o[i][j] = 0.f;

    const int maskv = maskp[0];
    const int tdiag = 2 * qt + (warp >> 2);
    const int ntiles = maskv ? (2 * qt + 2) : (SEQL / 64);

    __half* vhp = reinterpret_cast<__half*>(smw + FV_H);

    for (int t = 0; t < ntiles; t++) {
        const int kv0 = t * 64;

        if (t > 0) __syncthreads();
#pragma unroll
        for (int ii = 0; ii < 4; ii++) {
            int i = tid + ii * 256;
            int r = i >> 4, c4 = (i & 15) << 2;
            float4 k4 = *reinterpret_cast<const float4*>(K + (size_t)(kv0 + r) * DKH + c4);
            unsigned h01, l01, h23, l23;
            split_h2(k4.x, k4.y, h01, l01);
            split_h2(k4.z, k4.w, h23, l23);
            int kb = r * KW + (c4 >> 1);
            *reinterpret_cast<uint2*>(smw + FK_H + kb) = make_uint2(h01, h23);
            *reinterpret_cast<uint2*>(smw + FK_L + kb) = make_uint2(l01, l23);

            float4 v4 = *reinterpret_cast<const float4*>(V + (size_t)(kv0 + r) * DKH + c4);
            float vv[4] = { v4.x, v4.y, v4.z, v4.w };
            int p = r >> 1, rb = r & 1;
#pragma unroll
            for (int j = 0; j < 4; j++)
                vhp[(p * PW + c4 + j) * 2 + rb] = __float2half_rn(vv[j]);
        }
        __syncthreads();

        if (maskv && t > tdiag) continue;

        float s[8][4];
#pragma unroll
        for (int i = 0; i < 8; i++)
#pragma unroll
            for (int j = 0; j < 4; j++) s[i][j] = 0.f;

#pragma unroll
        for (int ks = 0; ks < 4; ks++) {
#pragma unroll
            for (int nt = 0; nt < 8; nt++) {
                int n = nt * 8 + r8;
                unsigned bh0 = smw[FK_H + n * KW + ks * 8 + lq];
                unsigned bh1 = smw[FK_H + n * KW + ks * 8 + lq + 4];
                unsigned bl0 = smw[FK_L + n * KW + ks * 8 + lq];
                unsigned bl1 = smw[FK_L + n * KW + ks * 8 + lq + 4];
                mma16h(s[nt], qh[ks][0], qh[ks][1], qh[ks][2], qh[ks][3], bh0, bh1);
                mma16h(s[nt], qh[ks][0], qh[ks][1], qh[ks][2], qh[ks][3], bl0, bl1);
                mma16h(s[nt], ql[ks][0], ql[ks][1], ql[ks][2], ql[ks][3], bh0, bh1);
            }
        }

        if (maskv && t == tdiag) {
            int rg0 = q0 + rl;
#pragma unroll
            for (int nt = 0; nt < 8; nt++) {
                int cg = kv0 + nt * 8 + lq * 2;
                if (cg > rg0)         s[nt][0] = -1e30f;
                if (cg + 1 > rg0)     s[nt][1] = -1e30f;
                if (cg > rg0 + 8)     s[nt][2] = -1e30f;
                if (cg + 1 > rg0 + 8) s[nt][3] = -1e30f;
            }
        }

#pragma unroll
        for (int sub = 0; sub < 2; sub++) {
            float tm = -1e30f;
#pragma unroll
            for (int nt = 0; nt < 8; nt++)
                tm = fmaxf(tm, fmaxf(s[nt][2 * sub], s[nt][2 * sub + 1]));
            tm = fmaxf(tm, __shfl_xor_sync(0xffffffffu, tm, 1));
            tm = fmaxf(tm, __shfl_xor_sync(0xffffffffu, tm, 2));
            float mn = fmaxf(m[sub], tm);
            float alpha = exp2f(m[sub] - mn);
            float rs = 0.f;
#pragma unroll
            for (int nt = 0; nt < 8; nt++) {
                float p0 = exp2f(s[nt][2 * sub] - mn);
                float p1 = exp2f(s[nt][2 * sub + 1] - mn);
                s[nt][2 * sub] = p0; s[nt][2 * sub + 1] = p1;
                rs += p0 + p1;
            }
            rs += __shfl_xor_sync(0xffffffffu, rs, 1);
            rs += __shfl_xor_sync(0xffffffffu, rs, 2);
            l[sub] = l[sub] * alpha + rs;
            m[sub] = mn;
#pragma unroll
            for (int dt = 0; dt < 8; dt++) {
                o[dt][2 * sub]     *= alpha;
                o[dt][2 * sub + 1] *= alpha;
            }
        }

        unsigned pa[4][4];
#pragma unroll
        for (int ks = 0; ks < 4; ks++) {
            pa[ks][0] = pack_h2(s[2*ks][0],   s[2*ks][1]);
            pa[ks][1] = pack_h2(s[2*ks][2],   s[2*ks][3]);
            pa[ks][2] = pack_h2(s[2*ks+1][0], s[2*ks+1][1]);
            pa[ks][3] = pack_h2(s[2*ks+1][2], s[2*ks+1][3]);
        }

        int ksmax = (maskv && t == tdiag) ? ((warp & 3) + 1) : 4;
#pragma unroll
        for (int ks = 0; ks < 4; ks++) {
            if (ks >= ksmax) break;
#pragma unroll
            for (int dt = 0; dt < 8; dt++) {
                int d = dt * 8 + r8;
                unsigned bh0 = smw[FV_H + (ks * 8 + lq) * PW + d];
                unsigned bh1 = smw[FV_H + (ks * 8 + lq + 4) * PW + d];
                mma16h(o[dt], pa[ks][0], pa[ks][1], pa[ks][2], pa[ks][3], bh0, bh1);
            }
        }
    }

    float i0 = 1.f / l[0];
    float i1 = 1.f / l[1];
    int rg = q0 + rl;
    size_t ob  = (((size_t)b * SEQL + rg) * NHEAD + h) * DKH;
    size_t ob2 = (((size_t)b * SEQL + rg + 8) * NHEAD + h) * DKH;
#pragma unroll
    for (int dt = 0; dt < 8; dt++) {
        int c = dt * 8 + lq * 2;
        g_attn[ob + c]      = o[dt][0] * i0;
        g_attn[ob + c + 1]  = o[dt][1] * i0;
        g_attn[ob2 + c]     = o[dt][2] * i1;
        g_attn[ob2 + c + 1] = o[dt][3] * i1;
    }
}

// ---------------- launcher ---------------------------------------------------
extern "C" void kernel_launch(void* const* d_in, const int* in_sizes, int n_in,
                              void* d_out, int out_size)
{
    const float* x_q = (const float*)d_in[0];
    const float* x_k = (const float*)d_in[1];
    const float* x_v = (const float*)d_in[2];
    const float* w_q = (const float*)d_in[3];
    const float* w_k = (const float*)d_in[4];
    const float* w_v = (const float*)d_in[5];
    const float* w_o = (const float*)d_in[6];
    const int*   msk = (const int*)d_in[7];
    float* out = (float*)d_out;

    cudaFuncSetAttribute((const void*)gemm_h_kernel<0,3>, cudaFuncAttributeMaxDynamicSharedMemorySize, GSM_BYTES);
    cudaFuncSetAttribute((const void*)gemm_h_kernel<0,2>, cudaFuncAttributeMaxDynamicSharedMemorySize, GSM_BYTES);
    cudaFuncSetAttribute((const void*)gemm_h_kernel<1,2>, cudaFuncAttributeMaxDynamicSharedMemorySize, GSM_BYTES);
    cudaFuncSetAttribute((const void*)flash_kernel, cudaFuncAttributeMaxDynamicSharedMemorySize, FSM_BYTES);

    // Q, K projections: fp16 x3, 2 heads per CTA
    gemm_h_kernel<0,3><<<dim3(MROWS / 128, NHEAD / 2, 2), 256, GSM_BYTES>>>(
        x_q, x_k, x_v, w_q, w_k, w_v, nullptr, 0);
    // V projection: fp16 x2
    gemm_h_kernel<0,2><<<dim3(MROWS / 128, NHEAD / 2, 1), 256, GSM_BYTES>>>(
        x_q, x_k, x_v, w_q, w_k, w_v, nullptr, 2);

    flash_kernel<<<dim3(SEQL / 128, BATCHN * NHEAD), 256, FSM_BYTES>>>(msk);

    // Output projection: fp16 x2
    gemm_h_kernel<1,2><<<dim3(MROWS / 128, EMB / 128, 1), 256, GSM_BYTES>>>(
        nullptr, nullptr, nullptr, w_o, nullptr, nullptr, out, 0);
}

// round 11
// speedup vs baseline: 3.6053x; 1.1343x over previous
#include <cuda_runtime.h>
#include <cuda_fp16.h>
#include <cstdint>

#define BATCHN 4
#define SEQL   2048
#define EMB    1024
#define NHEAD  16
#define DKH    64
#define MROWS  (BATCHN*SEQL)   /* 8192 */
#define BH     (BATCHN*NHEAD)  /* 64 */

// ---------------- scratch (static device globals; no runtime allocation) ----
// packed fp16 pairs: one uint = (hi half = even elem, high 16 bits = odd elem)
__device__ unsigned g_xh[3][(size_t)MROWS*512];   // x_q/x_k/x_v hi, [row][kpair]
__device__ unsigned g_xl[3][(size_t)MROWS*512];   // lo
__device__ unsigned g_wh[4][(size_t)512*1024];    // weights hi, [kpair][col] (col=head*64+d or n)
__device__ unsigned g_wl[4][(size_t)512*1024];
__device__ unsigned g_qh[(size_t)BH*SEQL*32];     // q hi (scaled by 8*log2e), [bh*S+s][dpair]
__device__ unsigned g_ql[(size_t)BH*SEQL*32];
__device__ unsigned g_kh[(size_t)BH*SEQL*32];
__device__ unsigned g_kl[(size_t)BH*SEQL*32];
__device__ unsigned g_vh[(size_t)BH*SEQL*32];     // v hi only
__device__ unsigned g_ah[(size_t)MROWS*512];      // attn out hi, [row][epair]
__device__ unsigned g_al[(size_t)MROWS*512];

#define LOG2E 1.4426950408889634f

// ---------------- helpers ---------------------------------------------------
__device__ __forceinline__ void mma16h(float c[4], unsigned a0, unsigned a1, unsigned a2, unsigned a3,
                                       unsigned b0, unsigned b1) {
    asm volatile(
        "mma.sync.aligned.m16n8k16.row.col.f32.f16.f16.f32 "
        "{%0,%1,%2,%3},{%4,%5,%6,%7},{%8,%9},{%0,%1,%2,%3};\n"
        : "+f"(c[0]), "+f"(c[1]), "+f"(c[2]), "+f"(c[3])
        : "r"(a0), "r"(a1), "r"(a2), "r"(a3), "r"(b0), "r"(b1));
}
__device__ __forceinline__ void split_h2(float x0, float x1, unsigned &hi, unsigned &lo) {
    __half2 H = __floats2half2_rn(x0, x1);
    float2 f = __half22float2(H);
    __half2 L = __floats2half2_rn(x0 - f.x, x1 - f.y);
    hi = *reinterpret_cast<unsigned*>(&H);
    lo = *reinterpret_cast<unsigned*>(&L);
}
__device__ __forceinline__ unsigned pack_h2(float x0, float x1) {
    __half2 H = __floats2half2_rn(x0, x1);
    return *reinterpret_cast<unsigned*>(&H);
}
__device__ __forceinline__ uint32_t smem_u32(const void* p) {
    uint32_t a;
    asm("{ .reg .u64 t; cvta.to.shared.u64 t, %1; cvt.u32.u64 %0, t; }" : "=r"(a) : "l"(p));
    return a;
}
#define CPA16(dst, src) asm volatile("cp.async.cg.shared.global [%0], [%1], 16;" :: "r"(dst), "l"(src))
#define CPA_COMMIT()    asm volatile("cp.async.commit_group;" ::: "memory")
#define CPA_WAIT0()     asm volatile("cp.async.wait_group 0;" ::: "memory")

// ---------------- conversion kernels -----------------------------------------
// x -> split packed pairs (pairs along k)
__global__ void __launch_bounds__(256) conv_x_kernel(
    const float* __restrict__ x0, const float* __restrict__ x1, const float* __restrict__ x2)
{
    int sel = blockIdx.z;
    const float* x = sel == 0 ? x0 : (sel == 1 ? x1 : x2);
    size_t idx = (size_t)blockIdx.x * 256 + threadIdx.x;   // word index, < MROWS*512
    float2 v = *reinterpret_cast<const float2*>(x + 2 * idx);
    unsigned h, l;
    split_h2(v.x, v.y, h, l);
    g_xh[sel][idx] = h;
    g_xl[sel][idx] = l;
}

// weights -> split packed [kpair][col]; col = head*64+d (proj) or n (w_o)
__global__ void __launch_bounds__(256) conv_w_kernel(
    const float* __restrict__ w0, const float* __restrict__ w1,
    const float* __restrict__ w2, const float* __restrict__ w3)
{
    int wsel = blockIdx.y;
    const float* W = wsel == 0 ? w0 : (wsel == 1 ? w1 : (wsel == 2 ? w2 : w3));
    size_t idx = (size_t)blockIdx.x * 256 + threadIdx.x;   // < 512*1024
    int p = (int)(idx >> 10);
    int col = (int)(idx & 1023);
    float v0, v1;
    if (wsel < 3) {
        int head = col >> 6, d = col & 63;
        size_t base = (size_t)head * EMB * 64 + (size_t)(2 * p) * 64 + d;
        v0 = W[base];
        v1 = W[base + 64];
    } else {
        v0 = W[(size_t)(2 * p) * EMB + col];
        v1 = W[(size_t)(2 * p + 1) * EMB + col];
    }
    unsigned h, l;
    split_h2(v0, v1, h, l);
    g_wh[wsel][idx] = h;
    g_wl[wsel][idx] = l;
}

// ---------------- GEMM (pre-split fp16, cp.async pipeline) -------------------
// A tile: [128 rows][AW=20 words] hi+lo.  B tile: [16 kpairs][BW=136 words] hi(+lo).
#define AW 20
#define BW 136
#define G_AH 0
#define G_AL (128*AW)
#define G_BH (2*128*AW)
#define G_BL (2*128*AW + 16*BW)
#define GSTAGE (2*128*AW + 2*16*BW)      /* 9472 words */
#define GSM_BYTES (2*GSTAGE*4)           /* 75776 bytes */

template<int MODE, int PASSES>
__global__ void __launch_bounds__(256, 2) gemm_p_kernel(float* __restrict__ Cext, int selbase)
{
    extern __shared__ unsigned smu[];
    const uint32_t sbase = smem_u32(smu);

    const int tid  = threadIdx.x;
    const int lane = tid & 31;
    const int warp = tid >> 5;
    const int wm = warp >> 1, wn = warp & 1;
    const int r8 = lane >> 2, lq = lane & 3;
    const int row0 = blockIdx.x * 128;
    const int col0 = blockIdx.y * 128;

    int sel = (MODE == 0) ? (blockIdx.z + selbase) : 3;
    const unsigned* Ahg = (MODE == 0) ? g_xh[sel] : g_ah;
    const unsigned* Alg = (MODE == 0) ? g_xl[sel] : g_al;
    const unsigned* Whg = g_wh[sel];
    const unsigned* Wlg = g_wl[sel];

    float acc[2][8][4];
#pragma unroll
    for (int i = 0; i < 2; i++)
#pragma unroll
        for (int j = 0; j < 8; j++)
#pragma unroll
            for (int r = 0; r < 4; r++) acc[i][j][r] = 0.f;

    // producer mapping
    const int am = tid & 127;          // A row
    const int ps = tid >> 7;           // A word part (words 8ps..8ps+7)

    // issue cp.async for chunk c into stage st
    auto issue = [&](int c, int st) {
        // A: hi + lo, 2 x 16B each
        {
            const unsigned* srcH = Ahg + (size_t)(row0 + am) * 512 + c * 16 + 8 * ps;
            const unsigned* srcL = Alg + (size_t)(row0 + am) * 512 + c * 16 + 8 * ps;
            uint32_t dH = sbase + (uint32_t)(st * GSTAGE + G_AH + am * AW + 8 * ps) * 4;
            uint32_t dL = sbase + (uint32_t)(st * GSTAGE + G_AL + am * AW + 8 * ps) * 4;
            CPA16(dH, srcH); CPA16(dH + 16, srcH + 4);
            CPA16(dL, srcL); CPA16(dL + 16, srcL + 4);
        }
        // B: 2 segs hi (+2 lo if x3)
#pragma unroll
        for (int a = 0; a < 2; a++) {
            int j = tid + a * 256;
            int p = j >> 5, cs = j & 31;
            const unsigned* srcH = Whg + (size_t)(c * 16 + p) * 1024 + col0 + cs * 4;
            uint32_t dH = sbase + (uint32_t)(st * GSTAGE + G_BH + p * BW + cs * 4) * 4;
            CPA16(dH, srcH);
            if (PASSES >= 3) {
                const unsigned* srcL = Wlg + (size_t)(c * 16 + p) * 1024 + col0 + cs * 4;
                uint32_t dL = sbase + (uint32_t)(st * GSTAGE + G_BL + p * BW + cs * 4) * 4;
                CPA16(dL, srcL);
            }
        }
        CPA_COMMIT();
    };

    issue(0, 0);

    for (int c = 0; c < EMB / 32; c++) {
        const int st = c & 1;
        CPA_WAIT0();
        __syncthreads();
        if (c + 1 < EMB / 32) issue(c + 1, st ^ 1);

        unsigned* Ah2 = smu + st * GSTAGE + G_AH;
        unsigned* Al2 = smu + st * GSTAGE + G_AL;
        unsigned* Bh2 = smu + st * GSTAGE + G_BH;
        unsigned* Bl2 = smu + st * GSTAGE + G_BL;

#pragma unroll
        for (int ks = 0; ks < 2; ks++) {
            const int kw = ks * 8;
            unsigned ah[2][4], al[2][4];
#pragma unroll
            for (int mt = 0; mt < 2; mt++) {
                int rw = (wm * 32 + mt * 16 + r8) * AW + kw + lq;
                ah[mt][0] = Ah2[rw];              al[mt][0] = Al2[rw];
                ah[mt][1] = Ah2[rw + 8 * AW];     al[mt][1] = Al2[rw + 8 * AW];
                ah[mt][2] = Ah2[rw + 4];          al[mt][2] = Al2[rw + 4];
                ah[mt][3] = Ah2[rw + 8 * AW + 4]; al[mt][3] = Al2[rw + 8 * AW + 4];
            }
#pragma unroll
            for (int nt = 0; nt < 8; nt++) {
                int n = wn * 64 + nt * 8 + r8;
                unsigned bh0 = Bh2[(kw + lq) * BW + n];
                unsigned bh1 = Bh2[(kw + 4 + lq) * BW + n];
#pragma unroll
                for (int mt = 0; mt < 2; mt++) {
                    mma16h(acc[mt][nt], ah[mt][0], ah[mt][1], ah[mt][2], ah[mt][3], bh0, bh1);
                    if (PASSES >= 2)
                        mma16h(acc[mt][nt], al[mt][0], al[mt][1], al[mt][2], al[mt][3], bh0, bh1);
                }
                if (PASSES >= 3) {
                    unsigned bl0 = Bl2[(kw + lq) * BW + n];
                    unsigned bl1 = Bl2[(kw + 4 + lq) * BW + n];
#pragma unroll
                    for (int mt = 0; mt < 2; mt++)
                        mma16h(acc[mt][nt], ah[mt][0], ah[mt][1], ah[mt][2], ah[mt][3], bl0, bl1);
                }
            }
        }
        __syncthreads();
    }

    // ---- epilogue ----
    const float qscale = 8.f * LOG2E;
#pragma unroll
    for (int mt = 0; mt < 2; mt++) {
        int r = row0 + wm * 32 + mt * 16 + r8;
#pragma unroll
        for (int nt = 0; nt < 8; nt++) {
            int cc = wn * 64 + nt * 8 + lq * 2;
            if (MODE == 0) {
                int b = r >> 11, s = r & 2047;
                int head = blockIdx.y * 2 + (cc >> 6);
                int w = (cc & 63) >> 1;
                size_t widx  = ((size_t)(b * NHEAD + head) * SEQL + s) * 32 + w;
                size_t widx2 = widx + (size_t)8 * 32;
                float v0 = acc[mt][nt][0], v1 = acc[mt][nt][1];
                float v2 = acc[mt][nt][2], v3 = acc[mt][nt][3];
                if (sel == 0) { v0 *= qscale; v1 *= qscale; v2 *= qscale; v3 *= qscale; }
                unsigned h0, l0, h1, l1;
                split_h2(v0, v1, h0, l0);
                split_h2(v2, v3, h1, l1);
                if (sel == 0) {
                    g_qh[widx] = h0;  g_ql[widx] = l0;
                    g_qh[widx2] = h1; g_ql[widx2] = l1;
                } else if (sel == 1) {
                    g_kh[widx] = h0;  g_kl[widx] = l0;
                    g_kh[widx2] = h1; g_kl[widx2] = l1;
                } else {
                    g_vh[widx] = h0;
                    g_vh[widx2] = h1;
                }
            } else {
                size_t base = (size_t)r * EMB + col0 + cc;
                Cext[base]               = acc[mt][nt][0];
                Cext[base + 1]           = acc[mt][nt][1];
                Cext[base + 8 * EMB]     = acc[mt][nt][2];
                Cext[base + 8 * EMB + 1] = acc[mt][nt][3];
            }
        }
    }
}

// ---------------- flash attention (causal), pre-split fp16 -------------------
#define QW 36
#define KW 36
#define PW 68
#define FQ_H 0
#define FQ_L (128*QW)
#define FK_H 0
#define FK_L (64*KW)
#define FV_H (2*64*KW)
#define FSM_WORDS (2*128*QW)
#define FSM_BYTES (FSM_WORDS*4)

__global__ void __launch_bounds__(256) flash_kernel(const int* __restrict__ maskp)
{
    extern __shared__ unsigned smw[];

    const int tid  = threadIdx.x;
    const int lane = tid & 31;
    const int warp = tid >> 5;
    const int r8 = lane >> 2, lq = lane & 3;
    const int qt = blockIdx.x;
    const int bh = blockIdx.y;
    const int b = bh >> 4, h = bh & 15;
    const int q0 = qt * 128;
    const size_t sb = (size_t)bh * SEQL;   // row base in q/k/v packed arrays

    // ---- stage Q tile (pure copy; already scaled + split) ----
#pragma unroll
    for (int ii = 0; ii < 4; ii++) {
        int i = tid + ii * 256;
        int r = i >> 3, sg = (i & 7) * 4;
        uint4 vh = *reinterpret_cast<const uint4*>(g_qh + (sb + q0 + r) * 32 + sg);
        uint4 vl = *reinterpret_cast<const uint4*>(g_ql + (sb + q0 + r) * 32 + sg);
        *reinterpret_cast<uint4*>(smw + FQ_H + r * QW + sg) = vh;
        *reinterpret_cast<uint4*>(smw + FQ_L + r * QW + sg) = vl;
    }
    __syncthreads();

    const int rl = warp * 16 + r8;
    unsigned qh[4][4], ql[4][4];
#pragma unroll
    for (int ks = 0; ks < 4; ks++) {
        int base = rl * QW + ks * 8 + lq;
        qh[ks][0] = smw[FQ_H + base];
        qh[ks][1] = smw[FQ_H + base + 8 * QW];
        qh[ks][2] = smw[FQ_H + base + 4];
        qh[ks][3] = smw[FQ_H + base + 8 * QW + 4];
        ql[ks][0] = smw[FQ_L + base];
        ql[ks][1] = smw[FQ_L + base + 8 * QW];
        ql[ks][2] = smw[FQ_L + base + 4];
        ql[ks][3] = smw[FQ_L + base + 8 * QW + 4];
    }
    __syncthreads();

    float m[2] = { -1e30f, -1e30f };
    float l[2] = { 0.f, 0.f };
    float o[8][4];
#pragma unroll
    for (int i = 0; i < 8; i++)
#pragma unroll
        for (int j = 0; j < 4; j++) o[i][j] = 0.f;

    const int maskv = maskp[0];
    const int tdiag = 2 * qt + (warp >> 2);
    const int ntiles = maskv ? (2 * qt + 2) : (SEQL / 64);

    __half* vhp = reinterpret_cast<__half*>(smw + FV_H);

    for (int t = 0; t < ntiles; t++) {
        const int kv0 = t * 64;

        if (t > 0) __syncthreads();
        // ---- K copy (hi + lo) ----
#pragma unroll
        for (int ii = 0; ii < 2; ii++) {
            int i = tid + ii * 256;
            int r = i >> 3, sg = (i & 7) * 4;
            uint4 vh = *reinterpret_cast<const uint4*>(g_kh + (sb + kv0 + r) * 32 + sg);
            uint4 vl = *reinterpret_cast<const uint4*>(g_kl + (sb + kv0 + r) * 32 + sg);
            *reinterpret_cast<uint4*>(smw + FK_H + r * KW + sg) = vh;
            *reinterpret_cast<uint4*>(smw + FK_L + r * KW + sg) = vl;
        }
        // ---- V copy + transpose (hi only) ----
#pragma unroll
        for (int ii = 0; ii < 4; ii++) {
            int i = tid + ii * 256;
            int r = i >> 4, c4 = (i & 15) << 2;
            uint2 w2 = *reinterpret_cast<const uint2*>(g_vh + (sb + kv0 + r) * 32 + (c4 >> 1));
            __half2 p0 = *reinterpret_cast<__half2*>(&w2.x);
            __half2 p1 = *reinterpret_cast<__half2*>(&w2.y);
            int p = r >> 1, rb = r & 1;
            vhp[(p * PW + c4 + 0) * 2 + rb] = __low2half(p0);
            vhp[(p * PW + c4 + 1) * 2 + rb] = __high2half(p0);
            vhp[(p * PW + c4 + 2) * 2 + rb] = __low2half(p1);
            vhp[(p * PW + c4 + 3) * 2 + rb] = __high2half(p1);
        }
        __syncthreads();

        if (maskv && t > tdiag) continue;

        // ---- S = Q K^T (fp16 x3) ----
        float s[8][4];
#pragma unroll
        for (int i = 0; i < 8; i++)
#pragma unroll
            for (int j = 0; j < 4; j++) s[i][j] = 0.f;

#pragma unroll
        for (int ks = 0; ks < 4; ks++) {
#pragma unroll
            for (int nt = 0; nt < 8; nt++) {
                int n = nt * 8 + r8;
                unsigned bh0 = smw[FK_H + n * KW + ks * 8 + lq];
                unsigned bh1 = smw[FK_H + n * KW + ks * 8 + lq + 4];
                unsigned bl0 = smw[FK_L + n * KW + ks * 8 + lq];
                unsigned bl1 = smw[FK_L + n * KW + ks * 8 + lq + 4];
                mma16h(s[nt], qh[ks][0], qh[ks][1], qh[ks][2], qh[ks][3], bh0, bh1);
                mma16h(s[nt], qh[ks][0], qh[ks][1], qh[ks][2], qh[ks][3], bl0, bl1);
                mma16h(s[nt], ql[ks][0], ql[ks][1], ql[ks][2], ql[ks][3], bh0, bh1);
            }
        }

        if (maskv && t == tdiag) {
            int rg0 = q0 + rl;
#pragma unroll
            for (int nt = 0; nt < 8; nt++) {
                int cg = kv0 + nt * 8 + lq * 2;
                if (cg > rg0)         s[nt][0] = -1e30f;
                if (cg + 1 > rg0)     s[nt][1] = -1e30f;
                if (cg > rg0 + 8)     s[nt][2] = -1e30f;
                if (cg + 1 > rg0 + 8) s[nt][3] = -1e30f;
            }
        }

        // ---- online softmax (base 2; scale folded into Q) ----
#pragma unroll
        for (int sub = 0; sub < 2; sub++) {
            float tm = -1e30f;
#pragma unroll
            for (int nt = 0; nt < 8; nt++)
                tm = fmaxf(tm, fmaxf(s[nt][2 * sub], s[nt][2 * sub + 1]));
            tm = fmaxf(tm, __shfl_xor_sync(0xffffffffu, tm, 1));
            tm = fmaxf(tm, __shfl_xor_sync(0xffffffffu, tm, 2));
            float mn = fmaxf(m[sub], tm);
            float alpha = exp2f(m[sub] - mn);
            float rs = 0.f;
#pragma unroll
            for (int nt = 0; nt < 8; nt++) {
                float p0 = exp2f(s[nt][2 * sub] - mn);
                float p1 = exp2f(s[nt][2 * sub + 1] - mn);
                s[nt][2 * sub] = p0; s[nt][2 * sub + 1] = p1;
                rs += p0 + p1;
            }
            rs += __shfl_xor_sync(0xffffffffu, rs, 1);
            rs += __shfl_xor_sync(0xffffffffu, rs, 2);
            l[sub] = l[sub] * alpha + rs;
            m[sub] = mn;
#pragma unroll
            for (int dt = 0; dt < 8; dt++) {
                o[dt][2 * sub]     *= alpha;
                o[dt][2 * sub + 1] *= alpha;
            }
        }

        // ---- pack P into A fragments (register-resident) ----
        unsigned pa[4][4];
#pragma unroll
        for (int ks = 0; ks < 4; ks++) {
            pa[ks][0] = pack_h2(s[2*ks][0],   s[2*ks][1]);
            pa[ks][1] = pack_h2(s[2*ks][2],   s[2*ks][3]);
            pa[ks][2] = pack_h2(s[2*ks+1][0], s[2*ks+1][1]);
            pa[ks][3] = pack_h2(s[2*ks+1][2], s[2*ks+1][3]);
        }

        // ---- O += P * V ----
        int ksmax = (maskv && t == tdiag) ? ((warp & 3) + 1) : 4;
#pragma unroll
        for (int ks = 0; ks < 4; ks++) {
            if (ks >= ksmax) break;
#pragma unroll
            for (int dt = 0; dt < 8; dt++) {
                int d = dt * 8 + r8;
                unsigned bh0 = smw[FV_H + (ks * 8 + lq) * PW + d];
                unsigned bh1 = smw[FV_H + (ks * 8 + lq + 4) * PW + d];
                mma16h(o[dt], pa[ks][0], pa[ks][1], pa[ks][2], pa[ks][3], bh0, bh1);
            }
        }
    }

    // ---- epilogue: write attn output pre-split packed ----
    float i0 = 1.f / l[0];
    float i1 = 1.f / l[1];
    int rg = q0 + rl;
    size_t row  = (size_t)(b * SEQL + rg) * 512;
    size_t row2 = row + (size_t)8 * 512;
#pragma unroll
    for (int dt = 0; dt < 8; dt++) {
        int w = h * 32 + dt * 4 + lq;
        unsigned h0, l0, h1, l1;
        split_h2(o[dt][0] * i0, o[dt][1] * i0, h0, l0);
        split_h2(o[dt][2] * i1, o[dt][3] * i1, h1, l1);
        g_ah[row + w]  = h0;  g_al[row + w]  = l0;
        g_ah[row2 + w] = h1;  g_al[row2 + w] = l1;
    }
}

// ---------------- launcher ---------------------------------------------------
extern "C" void kernel_launch(void* const* d_in, const int* in_sizes, int n_in,
                              void* d_out, int out_size)
{
    const float* x_q = (const float*)d_in[0];
    const float* x_k = (const float*)d_in[1];
    const float* x_v = (const float*)d_in[2];
    const float* w_q = (const float*)d_in[3];
    const float* w_k = (const float*)d_in[4];
    const float* w_v = (const float*)d_in[5];
    const float* w_o = (const float*)d_in[6];
    const int*   msk = (const int*)d_in[7];
    float* out = (float*)d_out;

    cudaFuncSetAttribute((const void*)gemm_p_kernel<0,3>, cudaFuncAttributeMaxDynamicSharedMemorySize, GSM_BYTES);
    cudaFuncSetAttribute((const void*)gemm_p_kernel<0,2>, cudaFuncAttributeMaxDynamicSharedMemorySize, GSM_BYTES);
    cudaFuncSetAttribute((const void*)gemm_p_kernel<1,2>, cudaFuncAttributeMaxDynamicSharedMemorySize, GSM_BYTES);
    cudaFuncSetAttribute((const void*)flash_kernel, cudaFuncAttributeMaxDynamicSharedMemorySize, FSM_BYTES);

    // one-time pre-split conversions
    conv_x_kernel<<<dim3(MROWS * 512 / 256, 1, 3), 256>>>(x_q, x_k, x_v);
    conv_w_kernel<<<dim3(512 * 1024 / 256, 4), 256>>>(w_q, w_k, w_v, w_o);

    // Q, K projections: fp16 x3 (Q scaled in epilogue)
    gemm_p_kernel<0,3><<<dim3(MROWS / 128, NHEAD / 2, 2), 256, GSM_BYTES>>>(nullptr, 0);
    // V projection: fp16 x2, hi-only output
    gemm_p_kernel<0,2><<<dim3(MROWS / 128, NHEAD / 2, 1), 256, GSM_BYTES>>>(nullptr, 2);

    flash_kernel<<<dim3(SEQL / 128, BH), 256, FSM_BYTES>>>(msk);

    // Output projection: fp16 x2
    gemm_p_kernel<1,2><<<dim3(MROWS / 128, EMB / 128, 1), 256, GSM_BYTES>>>(out, 0);
}